// round 7
// baseline (speedup 1.0000x reference)
#include <cuda_runtime.h>
#include <math.h>

#define BB 16
#define TT_ 81
#define DD 128
#define HH 8
#define BT (BB*TT_)       // 1296

// scratch (no allocation allowed)
__device__ float g_q[BB*HH*TT_*DD];
__device__ float g_v[BB*HH*TT_*DD];
__device__ float g_bo[BB*HH*TT_*DD];
__device__ float g_G[BT*DD];

// ---------------- packed fp32x2 helpers (sm_100+) ----------------
static __device__ __forceinline__ unsigned long long add2(unsigned long long a,
                                                          unsigned long long b) {
    unsigned long long r;
    asm("add.rn.f32x2 %0, %1, %2;" : "=l"(r) : "l"(a), "l"(b));
    return r;
}
static __device__ __forceinline__ unsigned long long fma2(unsigned long long a,
                                                          unsigned long long b,
                                                          unsigned long long c) {
    unsigned long long r;
    asm("fma.rn.f32x2 %0, %1, %2, %3;" : "=l"(r) : "l"(a), "l"(b), "l"(c));
    return r;
}
static __device__ __forceinline__ unsigned long long pack2(float x) {
    unsigned long long r;
    asm("mov.b64 %0, {%1, %1};" : "=l"(r) : "f"(x));
    return r;
}
static __device__ __forceinline__ float2 unpack2(unsigned long long v) {
    float2 f;
    asm("mov.b64 {%0, %1}, %2;" : "=f"(f.x), "=f"(f.y) : "l"(v));
    return f;
}
#define ABS2MASK 0x7FFFFFFF7FFFFFFFULL

#define XST_LD 90

// ---------------------------------------------------------------------------
// Kernel A: QKV GEMM. 256 blocks = (half(q/v), bh), 384 threads, 62.5KB smem
//  -> 2 blocks/SM. Each block: 81t x 128n x 128k, f32x2, writes g_q or g_v.
// ---------------------------------------------------------------------------
__global__ void __launch_bounds__(384)
qkv_kernel(const float* __restrict__ x,
           const float* __restrict__ wqkv_w,
           const float* __restrict__ wqkv_b,
           const float* __restrict__ head_en) {
    __shared__ float XsT[128*XST_LD];      // x transposed [d][t], t pad 81..89 = 0
    __shared__ float Ws[2][16][128];       // W chunk double buffer [k-local][n]

    const int half = blockIdx.x;           // 0 = q (n 0..127), 1 = v (n 128..255)
    const int bh   = blockIdx.y;
    const int b = bh >> 3, h = bh & 7;
    const int tid = threadIdx.x;

    // P0: x -> XsT
    {
        const float4* x4 = (const float4*)(x + (size_t)b*TT_*DD);
        for (int i = tid; i < TT_*DD/4; i += 384) {
            float4 xv = x4[i];
            int t  = i >> 5;
            int d0 = (i & 31) * 4;
            XsT[(d0+0)*XST_LD + t] = xv.x;
            XsT[(d0+1)*XST_LD + t] = xv.y;
            XsT[(d0+2)*XST_LD + t] = xv.z;
            XsT[(d0+3)*XST_LD + t] = xv.w;
        }
        for (int i = tid; i < 1152; i += 384) {
            int d = i / 9, t = 81 + (i % 9);
            XsT[d*XST_LD + t] = 0.f;
        }
    }

    const float* Wg = wqkv_w + ((size_t)(h*256 + half*128))*DD;   // 128 rows x 128
    const int wn  = tid & 127;
    const int wk8 = ((tid >> 7) & 1) * 8;   // only tid<256 stage
    if (tid < 256) {
        float4 wa = *(const float4*)(Wg + wn*DD + wk8);
        float4 wb = *(const float4*)(Wg + wn*DD + wk8 + 4);
        Ws[0][wk8+0][wn] = wa.x;  Ws[0][wk8+1][wn] = wa.y;
        Ws[0][wk8+2][wn] = wa.z;  Ws[0][wk8+3][wn] = wa.w;
        Ws[0][wk8+4][wn] = wb.x;  Ws[0][wk8+5][wn] = wb.y;
        Ws[0][wk8+6][wn] = wb.z;  Ws[0][wk8+7][wn] = wb.w;
    }
    __syncthreads();

    // P1: 11 warps x 8t, lane = 4n
    const int wrp  = tid >> 5;
    const int lane = tid & 31;
    const int t0 = wrp * 8;
    const int n0 = lane * 4;
    const bool act = (wrp < 11);

    unsigned long long acc[4][4];
#pragma unroll
    for (int i = 0; i < 4; i++)
#pragma unroll
        for (int j = 0; j < 4; j++) acc[i][j] = 0ULL;

    int buf = 0;
#pragma unroll 1
    for (int c = 0; c < 8; c++) {
        float4 wa, wb;
        if (c < 7 && tid < 256) {
            wa = *(const float4*)(Wg + wn*DD + (c+1)*16 + wk8);
            wb = *(const float4*)(Wg + wn*DD + (c+1)*16 + wk8 + 4);
        }
        if (act) {
#pragma unroll
            for (int kk = 0; kk < 16; kk++) {
                const int k = c*16 + kk;
                unsigned long long a0 = *(const unsigned long long*)&XsT[k*XST_LD + t0];
                unsigned long long a1 = *(const unsigned long long*)&XsT[k*XST_LD + t0 + 2];
                unsigned long long a2 = *(const unsigned long long*)&XsT[k*XST_LD + t0 + 4];
                unsigned long long a3 = *(const unsigned long long*)&XsT[k*XST_LD + t0 + 6];
                float4 w = *(const float4*)&Ws[buf][kk][n0];
                unsigned long long wp0 = pack2(w.x);
                unsigned long long wp1 = pack2(w.y);
                unsigned long long wp2 = pack2(w.z);
                unsigned long long wp3 = pack2(w.w);
                acc[0][0] = fma2(a0, wp0, acc[0][0]);
                acc[0][1] = fma2(a0, wp1, acc[0][1]);
                acc[0][2] = fma2(a0, wp2, acc[0][2]);
                acc[0][3] = fma2(a0, wp3, acc[0][3]);
                acc[1][0] = fma2(a1, wp0, acc[1][0]);
                acc[1][1] = fma2(a1, wp1, acc[1][1]);
                acc[1][2] = fma2(a1, wp2, acc[1][2]);
                acc[1][3] = fma2(a1, wp3, acc[1][3]);
                acc[2][0] = fma2(a2, wp0, acc[2][0]);
                acc[2][1] = fma2(a2, wp1, acc[2][1]);
                acc[2][2] = fma2(a2, wp2, acc[2][2]);
                acc[2][3] = fma2(a2, wp3, acc[2][3]);
                acc[3][0] = fma2(a3, wp0, acc[3][0]);
                acc[3][1] = fma2(a3, wp1, acc[3][1]);
                acc[3][2] = fma2(a3, wp2, acc[3][2]);
                acc[3][3] = fma2(a3, wp3, acc[3][3]);
            }
        }
        if (c < 7 && tid < 256) {
            int nb = buf ^ 1;
            Ws[nb][wk8+0][wn] = wa.x;  Ws[nb][wk8+1][wn] = wa.y;
            Ws[nb][wk8+2][wn] = wa.z;  Ws[nb][wk8+3][wn] = wa.w;
            Ws[nb][wk8+4][wn] = wb.x;  Ws[nb][wk8+5][wn] = wb.y;
            Ws[nb][wk8+6][wn] = wb.z;  Ws[nb][wk8+7][wn] = wb.w;
        }
        __syncthreads();
        buf ^= 1;
    }

    if (act) {
        const float sc = half ? head_en[h] : 1.0f;
        float* dst = (half ? g_v : g_q) + (size_t)bh*TT_*DD;
        float4 bia = *(const float4*)&wqkv_b[h*256 + half*128 + n0];
#pragma unroll
        for (int tp = 0; tp < 4; tp++) {
            float2 p0 = unpack2(acc[tp][0]);
            float2 p1 = unpack2(acc[tp][1]);
            float2 p2 = unpack2(acc[tp][2]);
            float2 p3 = unpack2(acc[tp][3]);
            int ta = t0 + 2*tp;
            int tb = ta + 1;
            if (ta < TT_) {
                float4 o;
                o.x = (p0.x + bia.x)*sc;  o.y = (p1.x + bia.y)*sc;
                o.z = (p2.x + bia.z)*sc;  o.w = (p3.x + bia.w)*sc;
                *(float4*)&dst[(size_t)ta*DD + n0] = o;
            }
            if (tb < TT_) {
                float4 o;
                o.x = (p0.y + bia.x)*sc;  o.y = (p1.y + bia.y)*sc;
                o.z = (p2.y + bia.z)*sc;  o.w = (p3.y + bia.w)*sc;
                *(float4*)&dst[(size_t)tb*DD + n0] = o;
            }
        }
    }
}

// ---------------------------------------------------------------------------
// Kernel B: attention core. 256 blocks = (t-half, bh), 512 threads, 80.3KB
// smem -> 2 blocks/SM.  Q-half from g_q; K recomputed; V staged into the dead
// KT region during softmax; scores/softmax/AV -> g_bo.
// ---------------------------------------------------------------------------
#define OFF_QS  0                      // Qs [44][128]           5632 fl
#define OFF_KT  (44*DD)                // KT [64 dp][168]       10752 fl  (Vs overlay)
#define S_LD    44
#define OFF_S   (OFF_KT + 64*168)      // S  [84][44]            3696 fl
#define SMEMB_FLOATS (OFF_S + 84*S_LD) // 20080 fl = 80320 B

__global__ void __launch_bounds__(512)
attn_core(const float* __restrict__ x,
          const float* __restrict__ wk_w,
          const float* __restrict__ msk,
          float* __restrict__ ap_out) {
    extern __shared__ float sm[];
    float* Qs = sm + OFF_QS;
    float* KT = sm + OFF_KT;           // per-d-pair stride 168 floats (negated k)
    float* Vs = sm + OFF_KT;           // overlay, valid after P2
    float* S  = sm + OFF_S;            // S[s][tLocal]

    const int half = blockIdx.x;
    const int bh   = blockIdx.y;
    const int b = bh >> 3, h = bh & 7;
    const int tid = threadIdx.x;
    const int tBeg = half * 41;
    const int nt   = half ? 40 : 41;

    // ---------------- P0 ----------------
    {
        const float4* q4 = (const float4*)(g_q + ((size_t)bh*TT_ + tBeg)*DD);
        for (int i = tid; i < nt*32; i += 512) ((float4*)Qs)[i] = q4[i];

        const float4* x4  = (const float4*)(x + (size_t)b*TT_*DD);
        const float4* wk4 = (const float4*)(wk_w + h*DD);
        for (int i = tid; i < TT_*DD/4; i += 512) {
            float4 xv = x4[i];
            float4 wv = wk4[i & 31];
            int t  = i >> 5;
            int dp = (i & 31) * 2;
            float2 k0, k1;
            k0.x = -(xv.x*wv.x); k0.y = -(xv.y*wv.y);
            k1.x = -(xv.z*wv.z); k1.y = -(xv.w*wv.w);
            *(float2*)&KT[(dp    )*168 + t*2] = k0;
            *(float2*)&KT[(dp + 1)*168 + t*2] = k1;
        }
        for (int i = tid; i < 192; i += 512) {          // KT s-pad 81..83
            int dp = i / 3, s = 81 + (i % 3);
            *(float2*)&KT[dp*168 + s*2] = make_float2(0.f, 0.f);
        }
        const float4 z4 = make_float4(0.f,0.f,0.f,0.f);
        for (int i = tid; i < 84*S_LD/4; i += 512)      // zero S (incl t-pad cols)
            ((float4*)S)[i] = z4;
    }
    __syncthreads();

    // ---------------- P2: scores, 4t x 2s per thread (451 active) ----------------
    const float scale = 0.08838834764831843f;   // 1/sqrt(128)
    if (tid < 451) {
        const int tt4 = tid / 41;
        const int ss2 = tid - tt4 * 41;
        const int t0s = tt4 * 4;
        const int s0  = ss2 * 2;
        int ti[4];
#pragma unroll
        for (int i = 0; i < 4; i++) ti[i] = min(t0s + i, nt - 1);

        unsigned long long sacc[4][2];
#pragma unroll
        for (int i = 0; i < 4; i++) { sacc[i][0] = 0ULL; sacc[i][1] = 0ULL; }

#pragma unroll 1
        for (int d = 0; d < DD; d += 4) {
            const int dp = d >> 1;
            ulonglong2 q[4];
#pragma unroll
            for (int i = 0; i < 4; i++)
                q[i] = *(const ulonglong2*)&Qs[ti[i]*DD + d];
            ulonglong2 ka = *(const ulonglong2*)&KT[(dp  )*168 + s0*2];  // s0,s0+1 @ d,d+1
            ulonglong2 kc = *(const ulonglong2*)&KT[(dp+1)*168 + s0*2];  // s0,s0+1 @ d+2,d+3
#pragma unroll
            for (int i = 0; i < 4; i++) {
                unsigned long long u;
                u = add2(q[i].x, ka.x) & ABS2MASK;  sacc[i][0] = add2(sacc[i][0], u);
                u = add2(q[i].y, kc.x) & ABS2MASK;  sacc[i][0] = add2(sacc[i][0], u);
                u = add2(q[i].x, ka.y) & ABS2MASK;  sacc[i][1] = add2(sacc[i][1], u);
                u = add2(q[i].y, kc.y) & ABS2MASK;  sacc[i][1] = add2(sacc[i][1], u);
            }
        }
#pragma unroll
        for (int i = 0; i < 4; i++) {
            if (t0s + i >= nt) continue;
#pragma unroll
            for (int j = 0; j < 2; j++) {
                if (s0 + j >= TT_) continue;
                float2 f = unpack2(sacc[i][j]);
                S[(s0 + j)*S_LD + (t0s + i)] = -(f.x + f.y) * scale;
            }
        }
    }
    __syncthreads();

    // ---------------- P3: softmax (warps 0-5) + V staging (warps 8-15) ----------------
    if (tid >= 256) {
        const float4* v4 = (const float4*)(g_v + (size_t)bh*TT_*DD);
        for (int i = tid - 256; i < TT_*DD/4; i += 256) ((float4*)Vs)[i] = v4[i];
    } else if (tid < 192) {
        const int t  = tid >> 2;        // 0..47 (guarded)
        const int l4 = tid & 3;
        const bool valid = (t < nt);
        const int sBeg = l4 * 21;
        const int sEnd = valid ? min(sBeg + 21, TT_) : sBeg;

        float mx = -1e30f;
        for (int s = sBeg; s < sEnd; s++) mx = fmaxf(mx, S[s*S_LD + t]);
        mx = fmaxf(mx, __shfl_xor_sync(0xFFFFFFFFu, mx, 1));
        mx = fmaxf(mx, __shfl_xor_sync(0xFFFFFFFFu, mx, 2));

        float sum = 0.f;
        for (int s = sBeg; s < sEnd; s++) {
            float e = __expf(S[s*S_LD + t] - mx);
            sum += e;
            S[s*S_LD + t] = e;
        }
        sum += __shfl_xor_sync(0xFFFFFFFFu, sum, 1);
        sum += __shfl_xor_sync(0xFFFFFFFFu, sum, 2);
        float inv = 1.f / sum;

        if (valid) {
            const int tg = tBeg + t;
            const float* mrow = msk + ((size_t)h*TT_ + tg)*TT_;
            for (int s = sBeg; s < sEnd; s++) {
                float mval = mrow[s];
                float a = S[s*S_LD + t] * inv * mval;
                S[s*S_LD + t] = a;
                if (b == 0)
                    ap_out[((size_t)tg*TT_ + s)*HH + h] = a - 1.f + mval;
            }
        }
    }
    __syncthreads();

    // ---------------- P4: AV, 2t x 8d per thread ----------------
    const int tp   = tid >> 4;
    const int doct = tid & 15;
    const int ntp  = (nt + 1) >> 1;
    if (tp < ntp) {
        const int t0a = 2 * tp;
        const int d0  = doct * 8;
        unsigned long long av[2][4];
#pragma unroll
        for (int i = 0; i < 2; i++)
#pragma unroll
            for (int j = 0; j < 4; j++) av[i][j] = 0ULL;

#pragma unroll 3
        for (int s = 0; s < TT_; s++) {
            float2 a2 = *(const float2*)&S[s*S_LD + t0a];    // pad col = 0
            ulonglong2 v0 = *(const ulonglong2*)&Vs[s*DD + d0];
            ulonglong2 v1 = *(const ulonglong2*)&Vs[s*DD + d0 + 4];
            unsigned long long pa = pack2(a2.x);
            unsigned long long pb = pack2(a2.y);
            av[0][0] = fma2(pa, v0.x, av[0][0]);
            av[0][1] = fma2(pa, v0.y, av[0][1]);
            av[0][2] = fma2(pa, v1.x, av[0][2]);
            av[0][3] = fma2(pa, v1.y, av[0][3]);
            av[1][0] = fma2(pb, v0.x, av[1][0]);
            av[1][1] = fma2(pb, v0.y, av[1][1]);
            av[1][2] = fma2(pb, v1.x, av[1][2]);
            av[1][3] = fma2(pb, v1.y, av[1][3]);
        }
        float* bo = g_bo + ((size_t)bh*TT_ + tBeg)*DD;
#pragma unroll
        for (int i = 0; i < 2; i++) {
            int t = t0a + i;
            if (t >= nt) continue;
            float2 p0 = unpack2(av[i][0]);
            float2 p1 = unpack2(av[i][1]);
            float2 p2 = unpack2(av[i][2]);
            float2 p3 = unpack2(av[i][3]);
            *(float4*)&bo[(size_t)t*DD + d0]     = make_float4(p0.x, p0.y, p1.x, p1.y);
            *(float4*)&bo[(size_t)t*DD + d0 + 4] = make_float4(p2.x, p2.y, p3.x, p3.y);
        }
    }
}

// ---------------------------------------------------------------------------
// Kernel C: G[m][d] = qgelu(sum_h bo)
// ---------------------------------------------------------------------------
__device__ __forceinline__ float qgelu4(float s) {
    float u = s + 4.f;
    return u / (1.f + __expf(-1.702f * u)) - 4.f;
}

__global__ void __launch_bounds__(128) reduce_gelu_kernel() {
    int idx = blockIdx.x * 128 + threadIdx.x;   // 0..41471
    int m  = idx >> 5;
    int kq = idx & 31;
    int bb = m / TT_, t = m - bb * TT_;
    const float4* base = (const float4*)g_bo + ((size_t)(bb*HH)*TT_ + t)*32 + kq;
    float s0 = 0.f, s1 = 0.f, s2 = 0.f, s3 = 0.f;
#pragma unroll
    for (int hh = 0; hh < HH; hh++) {
        float4 v = base[(size_t)hh*TT_*32];
        s0 += v.x; s1 += v.y; s2 += v.z; s3 += v.w;
    }
    float4 g;
    g.x = qgelu4(s0); g.y = qgelu4(s1); g.z = qgelu4(s2); g.w = qgelu4(s3);
    ((float4*)g_G)[(size_t)m*32 + kq] = g;
}

// ---------------------------------------------------------------------------
// Kernel D: out = x + G@Wf^T + bf.  162 blocks (16m x 64n), 256 threads.
// ---------------------------------------------------------------------------
__global__ void __launch_bounds__(256) fanout_kernel(const float* __restrict__ x,
                                                     const float* __restrict__ Wf,
                                                     const float* __restrict__ bf,
                                                     float* __restrict__ out) {
    extern __shared__ float sm[];
    float* Ws = sm;                 // [128][64]  Ws[k][n]
    float* Gs = sm + 128*64;        // [128][17]  Gs[k*17 + m]
    const int LDG_ = 17;
    const int mtile = blockIdx.x >> 1;
    const int halfn = blockIdx.x & 1;
    const int m0 = mtile * 16;
    const int nbase = halfn * 64;
    const int tid = threadIdx.x;

    {
        int n  = tid & 63;
        int k4 = tid >> 6;              // 0..3
        const float* wr = Wf + (size_t)(nbase + n) * DD;
#pragma unroll
        for (int p = 0; p < 8; p++) {
            int kq = p * 4 + k4;        // 0..31
            float4 w = *(const float4*)(wr + kq * 4);
            Ws[(kq*4+0)*64 + n] = w.x;
            Ws[(kq*4+1)*64 + n] = w.y;
            Ws[(kq*4+2)*64 + n] = w.z;
            Ws[(kq*4+3)*64 + n] = w.w;
        }
    }
    {
#pragma unroll
        for (int p = 0; p < 2; p++) {
            int i  = p * 256 + tid;     // 0..511
            int ml = i >> 5;
            int kq = i & 31;
            float4 g = ((const float4*)g_G)[(size_t)(m0 + ml)*32 + kq];
            Gs[(kq*4+0)*LDG_ + ml] = g.x;
            Gs[(kq*4+1)*LDG_ + ml] = g.y;
            Gs[(kq*4+2)*LDG_ + ml] = g.z;
            Gs[(kq*4+3)*LDG_ + ml] = g.w;
        }
    }
    __syncthreads();

    const int m_ = tid >> 4;            // 0..15
    const int n0 = (tid & 15) * 4;      // 0..60
    float a0 = 0.f, a1 = 0.f, a2 = 0.f, a3 = 0.f;
#pragma unroll 8
    for (int k = 0; k < 128; k++) {
        float g = Gs[k*LDG_ + m_];
        float4 w = *(const float4*)&Ws[k*64 + n0];
        a0 += g * w.x; a1 += g * w.y; a2 += g * w.z; a3 += g * w.w;
    }
    int m = m0 + m_;
    int ng = nbase + n0;
    float4 xv = *(const float4*)&x[(size_t)m*DD + ng];
    float4 bv = *(const float4*)&bf[ng];
    float4 o;
    o.x = xv.x + a0 + bv.x;
    o.y = xv.y + a1 + bv.y;
    o.z = xv.z + a2 + bv.z;
    o.w = xv.w + a3 + bv.w;
    *(float4*)&out[(size_t)m*DD + ng] = o;
}

// ---------------------------------------------------------------------------
extern "C" void kernel_launch(void* const* d_in, const int* in_sizes, int n_in,
                              void* d_out, int out_size) {
    const float* x        = (const float*)d_in[0];
    const float* msk      = (const float*)d_in[1];
    const float* wqkv_w   = (const float*)d_in[2];
    const float* wqkv_b   = (const float*)d_in[3];
    const float* wk_w     = (const float*)d_in[4];
    const float* fanout_w = (const float*)d_in[5];
    const float* fanout_b = (const float*)d_in[6];
    const float* head_en  = (const float*)d_in[7];

    float* out = (float*)d_out;
    float* ap_out = out + (size_t)BT * DD;   // 165888 onward

    const int smemB = SMEMB_FLOATS * 4;                  // 80320
    const int smemD = (128*64 + 128*17) * 4 + 16;        // ~41.5KB

    cudaFuncSetAttribute(attn_core,     cudaFuncAttributeMaxDynamicSharedMemorySize, smemB);
    cudaFuncSetAttribute(fanout_kernel, cudaFuncAttributeMaxDynamicSharedMemorySize, smemD);

    dim3 gridA(2, BB * HH);     // (q/v half, bh) = 256 blocks
    qkv_kernel<<<gridA, 384>>>(x, wqkv_w, wqkv_b, head_en);

    dim3 gridB(2, BB * HH);     // (t half, bh) = 256 blocks
    attn_core<<<gridB, 512, smemB>>>(x, wk_w, msk, ap_out);

    reduce_gelu_kernel<<<324, 128>>>();

    fanout_kernel<<<162, 256, smemD>>>(x, fanout_w, fanout_b, out);
}

// round 8
// speedup vs baseline: 1.1275x; 1.1275x over previous
#include <cuda_runtime.h>
#include <math.h>

#define BB 16
#define TT_ 81
#define DD 128
#define HH 8
#define BT (BB*TT_)       // 1296

// scratch (no allocation allowed)
__device__ float g_bo[BB*HH*TT_*DD];

// ---------------- packed fp32x2 helpers (sm_100+) ----------------
static __device__ __forceinline__ unsigned long long add2(unsigned long long a,
                                                          unsigned long long b) {
    unsigned long long r;
    asm("add.rn.f32x2 %0, %1, %2;" : "=l"(r) : "l"(a), "l"(b));
    return r;
}
static __device__ __forceinline__ unsigned long long fma2(unsigned long long a,
                                                          unsigned long long b,
                                                          unsigned long long c) {
    unsigned long long r;
    asm("fma.rn.f32x2 %0, %1, %2, %3;" : "=l"(r) : "l"(a), "l"(b), "l"(c));
    return r;
}
static __device__ __forceinline__ unsigned long long pack2(float x) {
    unsigned long long r;
    asm("mov.b64 %0, {%1, %1};" : "=l"(r) : "f"(x));
    return r;
}
static __device__ __forceinline__ float2 unpack2(unsigned long long v) {
    float2 f;
    asm("mov.b64 {%0, %1}, %2;" : "=f"(f.x), "=f"(f.y) : "l"(v));
    return f;
}
#define ABS2MASK 0x7FFFFFFF7FFFFFFFULL

// ---- fused-kernel smem layout (float offsets) ----
#define XST_LD   90
#define OFF_XST  0                        // XsT [128][90] (t 81..89 zero); Msk overlay after P1
#define OFF_KT   (128*XST_LD)             // 11520  KT2: 64 d-pairs x 84 s (float2, NEGATED k)
#define OFF_QS   (OFF_KT + 64*84*2)       // 22272  Qs [81][128]
#define OFF_VS   (OFF_QS + TT_*DD)        // 32640  Vs [81][128]
#define LDS_S    84
#define OFF_S    (OFF_VS + TT_*DD)        // 43008  S  [81][84]  S[s][t]
#define OFF_WS   (OFF_S + TT_*LDS_S)      // 49812  Ws [2][8][256]  (k-local x n)
#define SMEM_FLOATS (OFF_WS + 2*8*256)    // 53908 floats = 215632 bytes

// ---------------------------------------------------------------------------
// Fused kernel: one block per (b,h), 512 threads.
//  P0: conflict-free transposes (d-major jobs, lanes = consecutive t)
//  P1: QKV GEMM, 14 warps x 6 t-rows, chunk 8, t-packed f32x2 -> Qs, Vs
//  P2: scores -|q-k| (f32x2 + AND abs) ; warps 14/15 prefetch msk
//  P3: softmax over s (quad-parallel per t), *msk, ap (b==0)
//  P4: AV GEMM (fma2) -> g_bo
// ---------------------------------------------------------------------------
__global__ void __launch_bounds__(512, 1)
attn_fused(const float* __restrict__ x,
           const float* __restrict__ wqkv_w,
           const float* __restrict__ wqkv_b,
           const float* __restrict__ wk_w,
           const float* __restrict__ msk,
           const float* __restrict__ head_en,
           float* __restrict__ ap_out) {
    extern __shared__ float sm[];
    float* XsT = sm + OFF_XST;
    float* KT  = sm + OFF_KT;     // per-d-pair stride 168 floats
    float* Qs  = sm + OFF_QS;
    float* Vs  = sm + OFF_VS;
    float* S   = sm + OFF_S;
    float* Ws  = sm + OFF_WS;
    float* Msk = sm + OFF_XST;    // overlay (valid after P1)

    const int b = blockIdx.x >> 3;
    const int h = blockIdx.x & 7;
    const int tid = threadIdx.x;

    // ---------------- P0: loads (d-major: lanes span consecutive t) ----------
    {
        const float4* x4  = (const float4*)(x + (size_t)b*TT_*DD);
        const float4* wk4 = (const float4*)(wk_w + h*DD);
        for (int i = tid; i < 32*TT_; i += 512) {
            int dq = i / TT_;               // 0..31 (d-quad)
            int t  = i - dq * TT_;          // 0..80, consecutive across lanes
            float4 xv = x4[t*32 + dq];
            int d0 = dq * 4;
            XsT[(d0+0)*XST_LD + t] = xv.x;          // conflict-free STS.32
            XsT[(d0+1)*XST_LD + t] = xv.y;
            XsT[(d0+2)*XST_LD + t] = xv.z;
            XsT[(d0+3)*XST_LD + t] = xv.w;
            float4 wv = wk4[dq];
            int dp = dq * 2;
            float2 k0, k1;
            k0.x = -(xv.x*wv.x); k0.y = -(xv.y*wv.y);
            k1.x = -(xv.z*wv.z); k1.y = -(xv.w*wv.w);
            *(float2*)&KT[(dp    )*168 + t*2] = k0;  // conflict-free STS.64
            *(float2*)&KT[(dp + 1)*168 + t*2] = k1;
        }
        // zero XsT cols t = 81..89 for all 128 d
        for (int i = tid; i < 1152; i += 512) {
            int d = i / 9, t = 81 + (i % 9);
            XsT[d*XST_LD + t] = 0.f;
        }
        const float4 z4 = make_float4(0.f,0.f,0.f,0.f);
        for (int i = tid; i < TT_*LDS_S/4; i += 512)
            ((float4*)S)[i] = z4;
        for (int i = tid; i < 192; i += 512) {
            int dp = i / 3, s = 81 + (i % 3);
            *(float2*)&KT[dp*168 + s*2] = make_float2(0.f, 0.f);
        }
    }

    // W staging: chunk of 8 k-locals, thread loads one float4
    const float* Wg = wqkv_w + ((size_t)h * 2 * DD) * DD;   // 256 rows x 128
    const int wrow = tid >> 1;              // 0..255  (output n)
    const int wkq  = (tid & 1) * 4;         // k-local 0 or 4

    {   // stage chunk 0
        float4 w = *(const float4*)(Wg + wrow*DD + wkq);
        Ws[(wkq+0)*256 + wrow] = w.x;
        Ws[(wkq+1)*256 + wrow] = w.y;
        Ws[(wkq+2)*256 + wrow] = w.z;
        Ws[(wkq+3)*256 + wrow] = w.w;
    }
    __syncthreads();

    // ---------------- P1: QKV GEMM (14 warps x 6 t, chunk 8) ----------------
    const int wrp  = tid >> 5;
    const int lane = tid & 31;
    const int t0 = wrp * 6;                 // 0..78
    const int n0 = lane * 8;
    const bool gemm_act = (wrp < 14);

    unsigned long long acc[3][8];           // [t-pair][n]
#pragma unroll
    for (int i = 0; i < 3; i++)
#pragma unroll
        for (int j = 0; j < 8; j++) acc[i][j] = 0ULL;

    int buf = 0;
#pragma unroll 1
    for (int c = 0; c < 16; c++) {
        float4 wnext;
        if (c < 15) wnext = *(const float4*)(Wg + wrow*DD + (c+1)*8 + wkq);
        if (gemm_act) {
            const float* Wb = Ws + buf*2048;
#pragma unroll
            for (int kk = 0; kk < 8; kk++) {
                const int k = c*8 + kk;
                unsigned long long a0 = *(const unsigned long long*)&XsT[k*XST_LD + t0];
                unsigned long long a1 = *(const unsigned long long*)&XsT[k*XST_LD + t0 + 2];
                unsigned long long a2 = *(const unsigned long long*)&XsT[k*XST_LD + t0 + 4];
                float4 w0 = *(const float4*)&Wb[kk*256 + n0];
                float4 w1 = *(const float4*)&Wb[kk*256 + n0 + 4];
                unsigned long long wp[8];
                wp[0] = pack2(w0.x); wp[1] = pack2(w0.y);
                wp[2] = pack2(w0.z); wp[3] = pack2(w0.w);
                wp[4] = pack2(w1.x); wp[5] = pack2(w1.y);
                wp[6] = pack2(w1.z); wp[7] = pack2(w1.w);
#pragma unroll
                for (int j = 0; j < 8; j++) {
                    acc[0][j] = fma2(a0, wp[j], acc[0][j]);
                    acc[1][j] = fma2(a1, wp[j], acc[1][j]);
                    acc[2][j] = fma2(a2, wp[j], acc[2][j]);
                }
            }
        }
        if (c < 15) {
            float* Wb2 = Ws + (buf^1)*2048;
            Wb2[(wkq+0)*256 + wrow] = wnext.x;
            Wb2[(wkq+1)*256 + wrow] = wnext.y;
            Wb2[(wkq+2)*256 + wrow] = wnext.z;
            Wb2[(wkq+3)*256 + wrow] = wnext.w;
        }
        __syncthreads();
        buf ^= 1;
    }

    // epilogue: +bias, q -> Qs ; v -> Vs * head_en
    if (gemm_act) {
        const bool isv = (lane >= 16);
        const int d0 = (lane & 15) * 8;
        const float sc = isv ? head_en[h] : 1.0f;
        float* dst = isv ? Vs : Qs;
        float4 bia0 = *(const float4*)(wqkv_b + h*256 + n0);
        float4 bia1 = *(const float4*)(wqkv_b + h*256 + n0 + 4);
#pragma unroll
        for (int tp = 0; tp < 3; tp++) {
            float2 p[8];
#pragma unroll
            for (int j = 0; j < 8; j++) p[j] = unpack2(acc[tp][j]);
            int ta = t0 + 2*tp;
            int tb = ta + 1;
            if (ta < TT_) {
                float4 o0, o1;
                o0.x = (p[0].x + bia0.x)*sc;  o0.y = (p[1].x + bia0.y)*sc;
                o0.z = (p[2].x + bia0.z)*sc;  o0.w = (p[3].x + bia0.w)*sc;
                o1.x = (p[4].x + bia1.x)*sc;  o1.y = (p[5].x + bia1.y)*sc;
                o1.z = (p[6].x + bia1.z)*sc;  o1.w = (p[7].x + bia1.w)*sc;
                *(float4*)&dst[ta*DD + d0]     = o0;
                *(float4*)&dst[ta*DD + d0 + 4] = o1;
            }
            if (tb < TT_) {
                float4 o0, o1;
                o0.x = (p[0].y + bia0.x)*sc;  o0.y = (p[1].y + bia0.y)*sc;
                o0.z = (p[2].y + bia0.z)*sc;  o0.w = (p[3].y + bia0.w)*sc;
                o1.x = (p[4].y + bia1.x)*sc;  o1.y = (p[5].y + bia1.y)*sc;
                o1.z = (p[6].y + bia1.z)*sc;  o1.w = (p[7].y + bia1.w)*sc;
                *(float4*)&dst[tb*DD + d0]     = o0;
                *(float4*)&dst[tb*DD + d0 + 4] = o1;
            }
        }
    }
    __syncthreads();

    // ---------------- P2: scores (+ msk prefetch by warps 14/15) ----------------
    const float scale = 0.08838834764831843f;   // 1/sqrt(128)
    if (tid >= 448) {
        const float* mg = msk + (size_t)h * TT_ * TT_;
        for (int i = tid - 448; i < TT_*TT_; i += 64) Msk[i] = mg[i];
    } else if (tid < 441) {
        const int t0s = (tid / 21) * 4;
        const int s0 = (tid % 21) * 4;
        int ti[4];
#pragma unroll
        for (int i = 0; i < 4; i++) ti[i] = min(t0s + i, TT_ - 1);

        unsigned long long sacc[4][4];
#pragma unroll
        for (int i = 0; i < 4; i++)
#pragma unroll
            for (int j = 0; j < 4; j++) sacc[i][j] = 0ULL;

#pragma unroll 1
        for (int d = 0; d < DD; d += 4) {
            const int dp = d >> 1;
            ulonglong2 q[4];
#pragma unroll
            for (int i = 0; i < 4; i++)
                q[i] = *(const ulonglong2*)&Qs[ti[i]*DD + d];
            ulonglong2 ka = *(const ulonglong2*)&KT[(dp  )*168 + s0*2];
            ulonglong2 kb = *(const ulonglong2*)&KT[(dp  )*168 + s0*2 + 4];
            ulonglong2 kc = *(const ulonglong2*)&KT[(dp+1)*168 + s0*2];
            ulonglong2 kd = *(const ulonglong2*)&KT[(dp+1)*168 + s0*2 + 4];
#pragma unroll
            for (int i = 0; i < 4; i++) {
                unsigned long long u;
                u = add2(q[i].x, ka.x) & ABS2MASK;  sacc[i][0] = add2(sacc[i][0], u);
                u = add2(q[i].y, kc.x) & ABS2MASK;  sacc[i][0] = add2(sacc[i][0], u);
                u = add2(q[i].x, ka.y) & ABS2MASK;  sacc[i][1] = add2(sacc[i][1], u);
                u = add2(q[i].y, kc.y) & ABS2MASK;  sacc[i][1] = add2(sacc[i][1], u);
                u = add2(q[i].x, kb.x) & ABS2MASK;  sacc[i][2] = add2(sacc[i][2], u);
                u = add2(q[i].y, kd.x) & ABS2MASK;  sacc[i][2] = add2(sacc[i][2], u);
                u = add2(q[i].x, kb.y) & ABS2MASK;  sacc[i][3] = add2(sacc[i][3], u);
                u = add2(q[i].y, kd.y) & ABS2MASK;  sacc[i][3] = add2(sacc[i][3], u);
            }
        }
#pragma unroll
        for (int i = 0; i < 4; i++) {
            if (t0s + i >= TT_) continue;
#pragma unroll
            for (int j = 0; j < 4; j++) {
                if (s0 + j >= TT_) continue;
                float2 f = unpack2(sacc[i][j]);
                S[(s0 + j)*LDS_S + (t0s + i)] = -(f.x + f.y) * scale;
            }
        }
    }
    __syncthreads();

    // ---------------- P3: softmax over s (quad-parallel per t) ----------------
    if (tid < 352) {
        const int t  = tid >> 2;
        const int l4 = tid & 3;
        const bool valid = (t < TT_);
        const int sBeg = l4 * 21;
        const int sEnd = valid ? min(sBeg + 21, TT_) : sBeg;

        float mx = -1e30f;
        for (int s = sBeg; s < sEnd; s++) mx = fmaxf(mx, S[s*LDS_S + t]);
        mx = fmaxf(mx, __shfl_xor_sync(0xFFFFFFFFu, mx, 1));
        mx = fmaxf(mx, __shfl_xor_sync(0xFFFFFFFFu, mx, 2));

        float sum = 0.f;
        for (int s = sBeg; s < sEnd; s++) {
            float e = __expf(S[s*LDS_S + t] - mx);
            sum += e;
            S[s*LDS_S + t] = e;
        }
        sum += __shfl_xor_sync(0xFFFFFFFFu, sum, 1);
        sum += __shfl_xor_sync(0xFFFFFFFFu, sum, 2);
        float inv = 1.f / sum;

        for (int s = sBeg; s < sEnd; s++) {
            float mval = Msk[t*TT_ + s];
            float a = S[s*LDS_S + t] * inv * mval;
            S[s*LDS_S + t] = a;
            if (b == 0)
                ap_out[((size_t)t*TT_ + s)*HH + h] = a - 1.f + mval;
        }
    }
    __syncthreads();

    // ---------------- P4: AV GEMM -> g_bo ----------------
    float* bo = g_bo + (((size_t)b*HH + h)*TT_)*DD;
    if (tid < 336) {                      // 21 t-tiles x 16 d-tiles
        int t0a = (tid >> 4) * 4;
        int d0 = (tid & 15) * 8;
        unsigned long long av[4][4];
#pragma unroll
        for (int i = 0; i < 4; i++)
#pragma unroll
            for (int j = 0; j < 4; j++) av[i][j] = 0ULL;

#pragma unroll 2
        for (int s = 0; s < TT_; s++) {
            float4 a4 = *(const float4*)&S[s*LDS_S + t0a];   // pad cols are 0
            ulonglong2 v0 = *(const ulonglong2*)&Vs[s*DD + d0];
            ulonglong2 v1 = *(const ulonglong2*)&Vs[s*DD + d0 + 4];
            unsigned long long a0 = pack2(a4.x);
            unsigned long long a1 = pack2(a4.y);
            unsigned long long a2v = pack2(a4.z);
            unsigned long long a3 = pack2(a4.w);
            av[0][0] = fma2(a0, v0.x, av[0][0]);
            av[0][1] = fma2(a0, v0.y, av[0][1]);
            av[0][2] = fma2(a0, v1.x, av[0][2]);
            av[0][3] = fma2(a0, v1.y, av[0][3]);
            av[1][0] = fma2(a1, v0.x, av[1][0]);
            av[1][1] = fma2(a1, v0.y, av[1][1]);
            av[1][2] = fma2(a1, v1.x, av[1][2]);
            av[1][3] = fma2(a1, v1.y, av[1][3]);
            av[2][0] = fma2(a2v, v0.x, av[2][0]);
            av[2][1] = fma2(a2v, v0.y, av[2][1]);
            av[2][2] = fma2(a2v, v1.x, av[2][2]);
            av[2][3] = fma2(a2v, v1.y, av[2][3]);
            av[3][0] = fma2(a3, v0.x, av[3][0]);
            av[3][1] = fma2(a3, v0.y, av[3][1]);
            av[3][2] = fma2(a3, v1.x, av[3][2]);
            av[3][3] = fma2(a3, v1.y, av[3][3]);
        }
#pragma unroll
        for (int i = 0; i < 4; i++) {
            int t = t0a + i;
            if (t >= TT_) continue;
            float2 p0 = unpack2(av[i][0]);
            float2 p1 = unpack2(av[i][1]);
            float2 p2 = unpack2(av[i][2]);
            float2 p3 = unpack2(av[i][3]);
            *(float4*)&bo[(size_t)t*DD + d0]     = make_float4(p0.x, p0.y, p1.x, p1.y);
            *(float4*)&bo[(size_t)t*DD + d0 + 4] = make_float4(p2.x, p2.y, p3.x, p3.y);
        }
    }
}

// ---------------------------------------------------------------------------
// Kernel 2: out = x + qgelu(sum_h bo)@Wf^T + bf.
// Grid (2 n-halves, 162 m-tiles) = 324 blocks of 8 rows; head-reduce fused.
// smem ~37KB -> multiple blocks/SM hides the DRAM staging latency.
// ---------------------------------------------------------------------------
__device__ __forceinline__ float qgelu4(float s) {
    float u = s + 4.f;
    return u / (1.f + __expf(-1.702f * u)) - 4.f;
}

__global__ void __launch_bounds__(256) fanout_kernel(const float* __restrict__ x,
                                                     const float* __restrict__ Wf,
                                                     const float* __restrict__ bf,
                                                     float* __restrict__ out) {
    extern __shared__ float sm[];
    float* Ws = sm;                 // [128][64]  Ws[k][n]
    float* Gs = sm + 128*64;        // [128][9]   Gs[k*9 + m]
    const int LDG_ = 9;
    const int halfn = blockIdx.x;           // 0..1
    const int mtile = blockIdx.y;           // 0..161
    const int m0 = mtile * 8;
    const int nbase = halfn * 64;
    const int tid = threadIdx.x;

    // reduce heads + gelu -> Gs (1 job/thread: 8 m x 32 kq)
    {
        int ml = tid >> 5;          // 0..7
        int kq = tid & 31;
        int m = m0 + ml;
        int bb = m / TT_, t = m - bb * TT_;
        const float4* base = (const float4*)g_bo + ((size_t)(bb*HH)*TT_ + t)*32 + kq;
        float s0 = 0.f, s1 = 0.f, s2 = 0.f, s3 = 0.f;
#pragma unroll
        for (int hh = 0; hh < HH; hh++) {
            float4 v = base[(size_t)hh*TT_*32];
            s0 += v.x; s1 += v.y; s2 += v.z; s3 += v.w;
        }
        Gs[(kq*4+0)*LDG_ + ml] = qgelu4(s0);
        Gs[(kq*4+1)*LDG_ + ml] = qgelu4(s1);
        Gs[(kq*4+2)*LDG_ + ml] = qgelu4(s2);
        Gs[(kq*4+3)*LDG_ + ml] = qgelu4(s3);
    }
    // stage Wf half -> Ws[k][n]
    {
        int n  = tid & 63;
        int k4 = tid >> 6;              // 0..3
        const float* wr = Wf + (size_t)(nbase + n) * DD;
#pragma unroll
        for (int p = 0; p < 8; p++) {
            int kq = p * 4 + k4;        // 0..31
            float4 w = *(const float4*)(wr + kq * 4);
            Ws[(kq*4+0)*64 + n] = w.x;
            Ws[(kq*4+1)*64 + n] = w.y;
            Ws[(kq*4+2)*64 + n] = w.z;
            Ws[(kq*4+3)*64 + n] = w.w;
        }
    }
    __syncthreads();

    const int m_ = tid >> 5;            // 0..7
    const int n0 = (tid & 31) * 2;      // 0..62
    float a0 = 0.f, a1 = 0.f;
#pragma unroll 8
    for (int k = 0; k < 128; k++) {
        float g = Gs[k*LDG_ + m_];
        float2 w = *(const float2*)&Ws[k*64 + n0];
        a0 += g * w.x; a1 += g * w.y;
    }
    int m = m0 + m_;
    int ng = nbase + n0;
    float2 xv = *(const float2*)&x[(size_t)m*DD + ng];
    float2 bv = *(const float2*)&bf[ng];
    float2 o;
    o.x = xv.x + a0 + bv.x;
    o.y = xv.y + a1 + bv.y;
    *(float2*)&out[(size_t)m*DD + ng] = o;
}

// ---------------------------------------------------------------------------
extern "C" void kernel_launch(void* const* d_in, const int* in_sizes, int n_in,
                              void* d_out, int out_size) {
    const float* x        = (const float*)d_in[0];
    const float* msk      = (const float*)d_in[1];
    const float* wqkv_w   = (const float*)d_in[2];
    const float* wqkv_b   = (const float*)d_in[3];
    const float* wk_w     = (const float*)d_in[4];
    const float* fanout_w = (const float*)d_in[5];
    const float* fanout_b = (const float*)d_in[6];
    const float* head_en  = (const float*)d_in[7];

    float* out = (float*)d_out;
    float* ap_out = out + (size_t)BT * DD;   // 165888 onward

    const int smemA = SMEM_FLOATS * 4;                   // 215632
    const int smemF = (128*64 + 128*9) * 4;              // 37376

    cudaFuncSetAttribute(attn_fused,    cudaFuncAttributeMaxDynamicSharedMemorySize, smemA);
    cudaFuncSetAttribute(fanout_kernel, cudaFuncAttributeMaxDynamicSharedMemorySize, smemF);

    attn_fused<<<BB * HH, 512, smemA>>>(x, wqkv_w, wqkv_b, wk_w, msk, head_en, ap_out);

    dim3 gridF(2, 162);
    fanout_kernel<<<gridF, 256, smemF>>>(x, fanout_w, fanout_b, out);
}

// round 9
// speedup vs baseline: 1.1342x; 1.0059x over previous
#include <cuda_runtime.h>
#include <math.h>

#define BB 16
#define TT_ 81
#define DD 128
#define HH 8
#define BT (BB*TT_)       // 1296

// scratch (no allocation allowed)
__device__ float g_bo[BB*HH*TT_*DD];

// ---------------- packed fp32x2 helpers (sm_100+) ----------------
static __device__ __forceinline__ unsigned long long add2(unsigned long long a,
                                                          unsigned long long b) {
    unsigned long long r;
    asm("add.rn.f32x2 %0, %1, %2;" : "=l"(r) : "l"(a), "l"(b));
    return r;
}
static __device__ __forceinline__ unsigned long long fma2(unsigned long long a,
                                                          unsigned long long b,
                                                          unsigned long long c) {
    unsigned long long r;
    asm("fma.rn.f32x2 %0, %1, %2, %3;" : "=l"(r) : "l"(a), "l"(b), "l"(c));
    return r;
}
static __device__ __forceinline__ unsigned long long pack2(float x) {
    unsigned long long r;
    asm("mov.b64 %0, {%1, %1};" : "=l"(r) : "f"(x));
    return r;
}
static __device__ __forceinline__ float2 unpack2(unsigned long long v) {
    float2 f;
    asm("mov.b64 {%0, %1}, %2;" : "=f"(f.x), "=f"(f.y) : "l"(v));
    return f;
}
#define ABS2MASK 0x7FFFFFFF7FFFFFFFULL

// ---- fused-kernel smem layout (float offsets) ----
#define XST_LD   90
#define OFF_XST  0                        // XsT [128][90] (t 81..89 zero); Msk overlay after P1
#define OFF_KT   (128*XST_LD)             // 11520  KT2: 64 d-pairs x 84 s (float2, NEGATED k)
#define OFF_QS   (OFF_KT + 64*84*2)       // 22272  Qs [81][128]
#define OFF_VS   (OFF_QS + TT_*DD)        // 32640  Vs [81][128]
#define LDS_S    84
#define OFF_S    (OFF_VS + TT_*DD)        // 43008  S  [81][84]  S[s][t]
#define OFF_WS   (OFF_S + TT_*LDS_S)      // 49812  Ws [2][8][256]  (k-local x n)
#define SMEM_FLOATS (OFF_WS + 2*8*256)    // 53908 floats = 215632 bytes

// ---------------------------------------------------------------------------
// Fused kernel: one block per (b,h), 512 threads.
//  P0: conflict-free transposes (d-major jobs, lanes = consecutive t)
//  P1: QKV GEMM, 14 warps x 6 t-rows, chunk 8, t-packed f32x2 -> Qs, Vs
//  P2: scores -|q-k| (f32x2 + AND abs) ; warps 14/15 prefetch msk
//  P3: softmax over s (quad-parallel per t), *msk, ap (b==0)
//  P4: AV GEMM (fma2) -> g_bo
// ---------------------------------------------------------------------------
__global__ void __launch_bounds__(512, 1)
attn_fused(const float* __restrict__ x,
           const float* __restrict__ wqkv_w,
           const float* __restrict__ wqkv_b,
           const float* __restrict__ wk_w,
           const float* __restrict__ msk,
           const float* __restrict__ head_en,
           float* __restrict__ ap_out) {
    extern __shared__ float sm[];
    float* XsT = sm + OFF_XST;
    float* KT  = sm + OFF_KT;     // per-d-pair stride 168 floats
    float* Qs  = sm + OFF_QS;
    float* Vs  = sm + OFF_VS;
    float* S   = sm + OFF_S;
    float* Ws  = sm + OFF_WS;
    float* Msk = sm + OFF_XST;    // overlay (valid after P1)

    const int b = blockIdx.x >> 3;
    const int h = blockIdx.x & 7;
    const int tid = threadIdx.x;

    // ---------------- P0: loads (d-major: lanes span consecutive t) ----------
    {
        const float4* x4  = (const float4*)(x + (size_t)b*TT_*DD);
        const float4* wk4 = (const float4*)(wk_w + h*DD);
        for (int i = tid; i < 32*TT_; i += 512) {
            int dq = i / TT_;               // 0..31 (d-quad)
            int t  = i - dq * TT_;          // 0..80, consecutive across lanes
            float4 xv = x4[t*32 + dq];
            int d0 = dq * 4;
            XsT[(d0+0)*XST_LD + t] = xv.x;          // conflict-free STS.32
            XsT[(d0+1)*XST_LD + t] = xv.y;
            XsT[(d0+2)*XST_LD + t] = xv.z;
            XsT[(d0+3)*XST_LD + t] = xv.w;
            float4 wv = wk4[dq];
            int dp = dq * 2;
            float2 k0, k1;
            k0.x = -(xv.x*wv.x); k0.y = -(xv.y*wv.y);
            k1.x = -(xv.z*wv.z); k1.y = -(xv.w*wv.w);
            *(float2*)&KT[(dp    )*168 + t*2] = k0;  // conflict-free STS.64
            *(float2*)&KT[(dp + 1)*168 + t*2] = k1;
        }
        // zero XsT cols t = 81..89 for all 128 d
        for (int i = tid; i < 1152; i += 512) {
            int d = i / 9, t = 81 + (i % 9);
            XsT[d*XST_LD + t] = 0.f;
        }
        const float4 z4 = make_float4(0.f,0.f,0.f,0.f);
        for (int i = tid; i < TT_*LDS_S/4; i += 512)
            ((float4*)S)[i] = z4;
        for (int i = tid; i < 192; i += 512) {
            int dp = i / 3, s = 81 + (i % 3);
            *(float2*)&KT[dp*168 + s*2] = make_float2(0.f, 0.f);
        }
    }

    // W staging: chunk of 8 k-locals, thread loads one float4
    const float* Wg = wqkv_w + ((size_t)h * 2 * DD) * DD;   // 256 rows x 128
    const int wrow = tid >> 1;              // 0..255  (output n)
    const int wkq  = (tid & 1) * 4;         // k-local 0 or 4

    {   // stage chunk 0
        float4 w = *(const float4*)(Wg + wrow*DD + wkq);
        Ws[(wkq+0)*256 + wrow] = w.x;
        Ws[(wkq+1)*256 + wrow] = w.y;
        Ws[(wkq+2)*256 + wrow] = w.z;
        Ws[(wkq+3)*256 + wrow] = w.w;
    }
    __syncthreads();

    // ---------------- P1: QKV GEMM (14 warps x 6 t, chunk 8) ----------------
    const int wrp  = tid >> 5;
    const int lane = tid & 31;
    const int t0 = wrp * 6;                 // 0..78
    const int n0 = lane * 8;
    const bool gemm_act = (wrp < 14);

    unsigned long long acc[3][8];           // [t-pair][n]
#pragma unroll
    for (int i = 0; i < 3; i++)
#pragma unroll
        for (int j = 0; j < 8; j++) acc[i][j] = 0ULL;

    int buf = 0;
#pragma unroll 1
    for (int c = 0; c < 16; c++) {
        float4 wnext;
        if (c < 15) wnext = *(const float4*)(Wg + wrow*DD + (c+1)*8 + wkq);
        if (gemm_act) {
            const float* Wb = Ws + buf*2048;
#pragma unroll
            for (int kk = 0; kk < 8; kk++) {
                const int k = c*8 + kk;
                unsigned long long a0 = *(const unsigned long long*)&XsT[k*XST_LD + t0];
                unsigned long long a1 = *(const unsigned long long*)&XsT[k*XST_LD + t0 + 2];
                unsigned long long a2 = *(const unsigned long long*)&XsT[k*XST_LD + t0 + 4];
                float4 w0 = *(const float4*)&Wb[kk*256 + n0];
                float4 w1 = *(const float4*)&Wb[kk*256 + n0 + 4];
                unsigned long long wp[8];
                wp[0] = pack2(w0.x); wp[1] = pack2(w0.y);
                wp[2] = pack2(w0.z); wp[3] = pack2(w0.w);
                wp[4] = pack2(w1.x); wp[5] = pack2(w1.y);
                wp[6] = pack2(w1.z); wp[7] = pack2(w1.w);
#pragma unroll
                for (int j = 0; j < 8; j++) {
                    acc[0][j] = fma2(a0, wp[j], acc[0][j]);
                    acc[1][j] = fma2(a1, wp[j], acc[1][j]);
                    acc[2][j] = fma2(a2, wp[j], acc[2][j]);
                }
            }
        }
        if (c < 15) {
            float* Wb2 = Ws + (buf^1)*2048;
            Wb2[(wkq+0)*256 + wrow] = wnext.x;
            Wb2[(wkq+1)*256 + wrow] = wnext.y;
            Wb2[(wkq+2)*256 + wrow] = wnext.z;
            Wb2[(wkq+3)*256 + wrow] = wnext.w;
        }
        __syncthreads();
        buf ^= 1;
    }

    // epilogue: +bias, q -> Qs ; v -> Vs * head_en
    if (gemm_act) {
        const bool isv = (lane >= 16);
        const int d0 = (lane & 15) * 8;
        const float sc = isv ? head_en[h] : 1.0f;
        float* dst = isv ? Vs : Qs;
        float4 bia0 = *(const float4*)(wqkv_b + h*256 + n0);
        float4 bia1 = *(const float4*)(wqkv_b + h*256 + n0 + 4);
#pragma unroll
        for (int tp = 0; tp < 3; tp++) {
            float2 p[8];
#pragma unroll
            for (int j = 0; j < 8; j++) p[j] = unpack2(acc[tp][j]);
            int ta = t0 + 2*tp;
            int tb = ta + 1;
            if (ta < TT_) {
                float4 o0, o1;
                o0.x = (p[0].x + bia0.x)*sc;  o0.y = (p[1].x + bia0.y)*sc;
                o0.z = (p[2].x + bia0.z)*sc;  o0.w = (p[3].x + bia0.w)*sc;
                o1.x = (p[4].x + bia1.x)*sc;  o1.y = (p[5].x + bia1.y)*sc;
                o1.z = (p[6].x + bia1.z)*sc;  o1.w = (p[7].x + bia1.w)*sc;
                *(float4*)&dst[ta*DD + d0]     = o0;
                *(float4*)&dst[ta*DD + d0 + 4] = o1;
            }
            if (tb < TT_) {
                float4 o0, o1;
                o0.x = (p[0].y + bia0.x)*sc;  o0.y = (p[1].y + bia0.y)*sc;
                o0.z = (p[2].y + bia0.z)*sc;  o0.w = (p[3].y + bia0.w)*sc;
                o1.x = (p[4].y + bia1.x)*sc;  o1.y = (p[5].y + bia1.y)*sc;
                o1.z = (p[6].y + bia1.z)*sc;  o1.w = (p[7].y + bia1.w)*sc;
                *(float4*)&dst[tb*DD + d0]     = o0;
                *(float4*)&dst[tb*DD + d0 + 4] = o1;
            }
        }
    }
    __syncthreads();

    // ---------------- P2: scores (+ msk prefetch by warps 14/15) ----------------
    const float scale = 0.08838834764831843f;   // 1/sqrt(128)
    if (tid >= 448) {
        const float* mg = msk + (size_t)h * TT_ * TT_;
        for (int i = tid - 448; i < TT_*TT_; i += 64) Msk[i] = mg[i];
    } else if (tid < 441) {
        const int t0s = (tid / 21) * 4;
        const int s0 = (tid % 21) * 4;
        int ti[4];
#pragma unroll
        for (int i = 0; i < 4; i++) ti[i] = min(t0s + i, TT_ - 1);

        unsigned long long sacc[4][4];
#pragma unroll
        for (int i = 0; i < 4; i++)
#pragma unroll
            for (int j = 0; j < 4; j++) sacc[i][j] = 0ULL;

#pragma unroll 1
        for (int d = 0; d < DD; d += 4) {
            const int dp = d >> 1;
            ulonglong2 q[4];
#pragma unroll
            for (int i = 0; i < 4; i++)
                q[i] = *(const ulonglong2*)&Qs[ti[i]*DD + d];
            ulonglong2 ka = *(const ulonglong2*)&KT[(dp  )*168 + s0*2];
            ulonglong2 kb = *(const ulonglong2*)&KT[(dp  )*168 + s0*2 + 4];
            ulonglong2 kc = *(const ulonglong2*)&KT[(dp+1)*168 + s0*2];
            ulonglong2 kd = *(const ulonglong2*)&KT[(dp+1)*168 + s0*2 + 4];
#pragma unroll
            for (int i = 0; i < 4; i++) {
                unsigned long long u;
                u = add2(q[i].x, ka.x) & ABS2MASK;  sacc[i][0] = add2(sacc[i][0], u);
                u = add2(q[i].y, kc.x) & ABS2MASK;  sacc[i][0] = add2(sacc[i][0], u);
                u = add2(q[i].x, ka.y) & ABS2MASK;  sacc[i][1] = add2(sacc[i][1], u);
                u = add2(q[i].y, kc.y) & ABS2MASK;  sacc[i][1] = add2(sacc[i][1], u);
                u = add2(q[i].x, kb.x) & ABS2MASK;  sacc[i][2] = add2(sacc[i][2], u);
                u = add2(q[i].y, kd.x) & ABS2MASK;  sacc[i][2] = add2(sacc[i][2], u);
                u = add2(q[i].x, kb.y) & ABS2MASK;  sacc[i][3] = add2(sacc[i][3], u);
                u = add2(q[i].y, kd.y) & ABS2MASK;  sacc[i][3] = add2(sacc[i][3], u);
            }
        }
#pragma unroll
        for (int i = 0; i < 4; i++) {
            if (t0s + i >= TT_) continue;
#pragma unroll
            for (int j = 0; j < 4; j++) {
                if (s0 + j >= TT_) continue;
                float2 f = unpack2(sacc[i][j]);
                S[(s0 + j)*LDS_S + (t0s + i)] = -(f.x + f.y) * scale;
            }
        }
    }
    __syncthreads();

    // ---------------- P3: softmax over s (quad-parallel per t) ----------------
    if (tid < 352) {
        const int t  = tid >> 2;
        const int l4 = tid & 3;
        const bool valid = (t < TT_);
        const int sBeg = l4 * 21;
        const int sEnd = valid ? min(sBeg + 21, TT_) : sBeg;

        float mx = -1e30f;
        for (int s = sBeg; s < sEnd; s++) mx = fmaxf(mx, S[s*LDS_S + t]);
        mx = fmaxf(mx, __shfl_xor_sync(0xFFFFFFFFu, mx, 1));
        mx = fmaxf(mx, __shfl_xor_sync(0xFFFFFFFFu, mx, 2));

        float sum = 0.f;
        for (int s = sBeg; s < sEnd; s++) {
            float e = __expf(S[s*LDS_S + t] - mx);
            sum += e;
            S[s*LDS_S + t] = e;
        }
        sum += __shfl_xor_sync(0xFFFFFFFFu, sum, 1);
        sum += __shfl_xor_sync(0xFFFFFFFFu, sum, 2);
        float inv = 1.f / sum;

        for (int s = sBeg; s < sEnd; s++) {
            float mval = Msk[t*TT_ + s];
            float a = S[s*LDS_S + t] * inv * mval;
            S[s*LDS_S + t] = a;
            if (b == 0)
                ap_out[((size_t)t*TT_ + s)*HH + h] = a - 1.f + mval;
        }
    }
    __syncthreads();

    // ---------------- P4: AV GEMM -> g_bo ----------------
    float* bo = g_bo + (((size_t)b*HH + h)*TT_)*DD;
    if (tid < 336) {                      // 21 t-tiles x 16 d-tiles
        int t0a = (tid >> 4) * 4;
        int d0 = (tid & 15) * 8;
        unsigned long long av[4][4];
#pragma unroll
        for (int i = 0; i < 4; i++)
#pragma unroll
            for (int j = 0; j < 4; j++) av[i][j] = 0ULL;

#pragma unroll 2
        for (int s = 0; s < TT_; s++) {
            float4 a4 = *(const float4*)&S[s*LDS_S + t0a];   // pad cols are 0
            ulonglong2 v0 = *(const ulonglong2*)&Vs[s*DD + d0];
            ulonglong2 v1 = *(const ulonglong2*)&Vs[s*DD + d0 + 4];
            unsigned long long a0 = pack2(a4.x);
            unsigned long long a1 = pack2(a4.y);
            unsigned long long a2v = pack2(a4.z);
            unsigned long long a3 = pack2(a4.w);
            av[0][0] = fma2(a0, v0.x, av[0][0]);
            av[0][1] = fma2(a0, v0.y, av[0][1]);
            av[0][2] = fma2(a0, v1.x, av[0][2]);
            av[0][3] = fma2(a0, v1.y, av[0][3]);
            av[1][0] = fma2(a1, v0.x, av[1][0]);
            av[1][1] = fma2(a1, v0.y, av[1][1]);
            av[1][2] = fma2(a1, v1.x, av[1][2]);
            av[1][3] = fma2(a1, v1.y, av[1][3]);
            av[2][0] = fma2(a2v, v0.x, av[2][0]);
            av[2][1] = fma2(a2v, v0.y, av[2][1]);
            av[2][2] = fma2(a2v, v1.x, av[2][2]);
            av[2][3] = fma2(a2v, v1.y, av[2][3]);
            av[3][0] = fma2(a3, v0.x, av[3][0]);
            av[3][1] = fma2(a3, v0.y, av[3][1]);
            av[3][2] = fma2(a3, v1.x, av[3][2]);
            av[3][3] = fma2(a3, v1.y, av[3][3]);
        }
#pragma unroll
        for (int i = 0; i < 4; i++) {
            int t = t0a + i;
            if (t >= TT_) continue;
            float2 p0 = unpack2(av[i][0]);
            float2 p1 = unpack2(av[i][1]);
            float2 p2 = unpack2(av[i][2]);
            float2 p3 = unpack2(av[i][3]);
            *(float4*)&bo[(size_t)t*DD + d0]     = make_float4(p0.x, p0.y, p1.x, p1.y);
            *(float4*)&bo[(size_t)t*DD + d0 + 4] = make_float4(p2.x, p2.y, p3.x, p3.y);
        }
    }
}

// ---------------------------------------------------------------------------
// Kernel 2: out = x + qgelu(sum_h bo)@Wf^T + bf.
// Grid (2 n-halves, 162 m-tiles) = 324 blocks of 8 rows; head-reduce fused.
// smem ~37KB -> multiple blocks/SM hides the DRAM staging latency.
// ---------------------------------------------------------------------------
__device__ __forceinline__ float qgelu4(float s) {
    float u = s + 4.f;
    return u / (1.f + __expf(-1.702f * u)) - 4.f;
}

__global__ void __launch_bounds__(256) fanout_kernel(const float* __restrict__ x,
                                                     const float* __restrict__ Wf,
                                                     const float* __restrict__ bf,
                                                     float* __restrict__ out) {
    extern __shared__ float sm[];
    float* Ws = sm;                 // [128][64]  Ws[k][n]
    float* Gs = sm + 128*64;        // [128][9]   Gs[k*9 + m]
    const int LDG_ = 9;
    const int halfn = blockIdx.x;           // 0..1
    const int mtile = blockIdx.y;           // 0..161
    const int m0 = mtile * 8;
    const int nbase = halfn * 64;
    const int tid = threadIdx.x;

    // reduce heads + gelu -> Gs (1 job/thread: 8 m x 32 kq)
    {
        int ml = tid >> 5;          // 0..7
        int kq = tid & 31;
        int m = m0 + ml;
        int bb = m / TT_, t = m - bb * TT_;
        const float4* base = (const float4*)g_bo + ((size_t)(bb*HH)*TT_ + t)*32 + kq;
        float s0 = 0.f, s1 = 0.f, s2 = 0.f, s3 = 0.f;
#pragma unroll
        for (int hh = 0; hh < HH; hh++) {
            float4 v = base[(size_t)hh*TT_*32];
            s0 += v.x; s1 += v.y; s2 += v.z; s3 += v.w;
        }
        Gs[(kq*4+0)*LDG_ + ml] = qgelu4(s0);
        Gs[(kq*4+1)*LDG_ + ml] = qgelu4(s1);
        Gs[(kq*4+2)*LDG_ + ml] = qgelu4(s2);
        Gs[(kq*4+3)*LDG_ + ml] = qgelu4(s3);
    }
    // stage Wf half -> Ws[k][n]
    {
        int n  = tid & 63;
        int k4 = tid >> 6;              // 0..3
        const float* wr = Wf + (size_t)(nbase + n) * DD;
#pragma unroll
        for (int p = 0; p < 8; p++) {
            int kq = p * 4 + k4;        // 0..31
            float4 w = *(const float4*)(wr + kq * 4);
            Ws[(kq*4+0)*64 + n] = w.x;
            Ws[(kq*4+1)*64 + n] = w.y;
            Ws[(kq*4+2)*64 + n] = w.z;
            Ws[(kq*4+3)*64 + n] = w.w;
        }
    }
    __syncthreads();

    const int m_ = tid >> 5;            // 0..7
    const int n0 = (tid & 31) * 2;      // 0..62
    float a0 = 0.f, a1 = 0.f;
#pragma unroll 8
    for (int k = 0; k < 128; k++) {
        float g = Gs[k*LDG_ + m_];
        float2 w = *(const float2*)&Ws[k*64 + n0];
        a0 += g * w.x; a1 += g * w.y;
    }
    int m = m0 + m_;
    int ng = nbase + n0;
    float2 xv = *(const float2*)&x[(size_t)m*DD + ng];
    float2 bv = *(const float2*)&bf[ng];
    float2 o;
    o.x = xv.x + a0 + bv.x;
    o.y = xv.y + a1 + bv.y;
    *(float2*)&out[(size_t)m*DD + ng] = o;
}

// ---------------------------------------------------------------------------
extern "C" void kernel_launch(void* const* d_in, const int* in_sizes, int n_in,
                              void* d_out, int out_size) {
    const float* x        = (const float*)d_in[0];
    const float* msk      = (const float*)d_in[1];
    const float* wqkv_w   = (const float*)d_in[2];
    const float* wqkv_b   = (const float*)d_in[3];
    const float* wk_w     = (const float*)d_in[4];
    const float* fanout_w = (const float*)d_in[5];
    const float* fanout_b = (const float*)d_in[6];
    const float* head_en  = (const float*)d_in[7];

    float* out = (float*)d_out;
    float* ap_out = out + (size_t)BT * DD;   // 165888 onward

    const int smemA = SMEM_FLOATS * 4;                   // 215632
    const int smemF = (128*64 + 128*9) * 4;              // 37376

    cudaFuncSetAttribute(attn_fused,    cudaFuncAttributeMaxDynamicSharedMemorySize, smemA);
    cudaFuncSetAttribute(fanout_kernel, cudaFuncAttributeMaxDynamicSharedMemorySize, smemF);

    attn_fused<<<BB * HH, 512, smemA>>>(x, wqkv_w, wqkv_b, wk_w, msk, head_en, ap_out);

    dim3 gridF(2, 162);
    fanout_kernel<<<gridF, 256, smemF>>>(x, fanout_w, fanout_b, out);
}

// round 10
// speedup vs baseline: 1.1623x; 1.0248x over previous
#include <cuda_runtime.h>
#include <math.h>

#define BB 16
#define TT_ 81
#define DD 128
#define HH 8
#define BT (BB*TT_)       // 1296

// scratch (no allocation allowed)
__device__ float g_bo[BB*HH*TT_*DD];
__device__ float g_G[BT*DD];

// ---------------- packed fp32x2 helpers (sm_100+) ----------------
static __device__ __forceinline__ unsigned long long add2(unsigned long long a,
                                                          unsigned long long b) {
    unsigned long long r;
    asm("add.rn.f32x2 %0, %1, %2;" : "=l"(r) : "l"(a), "l"(b));
    return r;
}
static __device__ __forceinline__ unsigned long long fma2(unsigned long long a,
                                                          unsigned long long b,
                                                          unsigned long long c) {
    unsigned long long r;
    asm("fma.rn.f32x2 %0, %1, %2, %3;" : "=l"(r) : "l"(a), "l"(b), "l"(c));
    return r;
}
static __device__ __forceinline__ unsigned long long pack2(float x) {
    unsigned long long r;
    asm("mov.b64 %0, {%1, %1};" : "=l"(r) : "f"(x));
    return r;
}
static __device__ __forceinline__ float2 unpack2(unsigned long long v) {
    float2 f;
    asm("mov.b64 {%0, %1}, %2;" : "=f"(f.x), "=f"(f.y) : "l"(v));
    return f;
}
#define ABS2MASK 0x7FFFFFFF7FFFFFFFULL

// ---- fused-kernel smem layout (float offsets) ----
#define XST_LD   90
#define OFF_XST  0                        // XsT [128][90] (t 81..89 zero); Msk overlay after P1
#define OFF_KT   (128*XST_LD)             // 11520  KT2: 64 d-pairs x 84 s (float2, NEGATED k)
#define OFF_QS   (OFF_KT + 64*84*2)       // 22272  Qs [81][128]
#define OFF_VS   (OFF_QS + TT_*DD)        // 32640  Vs [81][128]
#define LDS_S    84
#define OFF_S    (OFF_VS + TT_*DD)        // 43008  S  [81][84]  S[s][t]
#define OFF_WS   (OFF_S + TT_*LDS_S)      // 49812  Ws [2][8][256]
#define SMEM_FLOATS (OFF_WS + 2*8*256)    // 53908 floats = 215632 bytes

// ---------------------------------------------------------------------------
// Fused attention kernel (R5-proven config): one block per (b,h), 512 threads.
// ---------------------------------------------------------------------------
__global__ void __launch_bounds__(512, 1)
attn_fused(const float* __restrict__ x,
           const float* __restrict__ wqkv_w,
           const float* __restrict__ wqkv_b,
           const float* __restrict__ wk_w,
           const float* __restrict__ msk,
           const float* __restrict__ head_en,
           float* __restrict__ ap_out) {
    extern __shared__ float sm[];
    float* XsT = sm + OFF_XST;
    float* KT  = sm + OFF_KT;     // per-d-pair stride 168 floats
    float* Qs  = sm + OFF_QS;
    float* Vs  = sm + OFF_VS;
    float* S   = sm + OFF_S;
    float* Ws  = sm + OFF_WS;
    float* Msk = sm + OFF_XST;    // overlay (valid after P1)

    const int b = blockIdx.x >> 3;
    const int h = blockIdx.x & 7;
    const int tid = threadIdx.x;

    // ---------------- P0: loads ----------------
    {
        const float4* x4  = (const float4*)(x + (size_t)b*TT_*DD);
        const float4* wk4 = (const float4*)(wk_w + h*DD);
        for (int i = tid; i < TT_*DD/4; i += 512) {
            float4 xv = x4[i];
            int t  = i >> 5;
            int d0 = (i & 31) * 4;
            XsT[(d0+0)*XST_LD + t] = xv.x;
            XsT[(d0+1)*XST_LD + t] = xv.y;
            XsT[(d0+2)*XST_LD + t] = xv.z;
            XsT[(d0+3)*XST_LD + t] = xv.w;
            float4 wv = wk4[i & 31];
            int dp = (i & 31) * 2;
            float2 k0, k1;
            k0.x = -(xv.x*wv.x); k0.y = -(xv.y*wv.y);
            k1.x = -(xv.z*wv.z); k1.y = -(xv.w*wv.w);
            *(float2*)&KT[(dp    )*168 + t*2] = k0;
            *(float2*)&KT[(dp + 1)*168 + t*2] = k1;
        }
        for (int i = tid; i < 1152; i += 512) {
            int d = i / 9, t = 81 + (i % 9);
            XsT[d*XST_LD + t] = 0.f;
        }
        const float4 z4 = make_float4(0.f,0.f,0.f,0.f);
        for (int i = tid; i < TT_*LDS_S/4; i += 512)
            ((float4*)S)[i] = z4;
        for (int i = tid; i < 192; i += 512) {
            int dp = i / 3, s = 81 + (i % 3);
            *(float2*)&KT[dp*168 + s*2] = make_float2(0.f, 0.f);
        }
    }

    const float* Wg = wqkv_w + ((size_t)h * 2 * DD) * DD;   // 256 rows x 128
    const int wrow = tid >> 1;              // 0..255  (output n)
    const int wkq  = (tid & 1) * 4;         // k-local 0 or 4

    {   // stage chunk 0
        float4 w = *(const float4*)(Wg + wrow*DD + wkq);
        Ws[(wkq+0)*256 + wrow] = w.x;
        Ws[(wkq+1)*256 + wrow] = w.y;
        Ws[(wkq+2)*256 + wrow] = w.z;
        Ws[(wkq+3)*256 + wrow] = w.w;
    }
    __syncthreads();

    // ---------------- P1: QKV GEMM (11 warps x 8 t, chunk 8, t-pair lanes) ----
    const int tt = tid >> 5;
    const int nn = tid & 31;
    const int t0 = tt * 8;
    const int n0 = nn * 8;
    const bool gemm_act = (tt < 11);

    unsigned long long acc[4][8];           // [t-pair][n]
#pragma unroll
    for (int i = 0; i < 4; i++)
#pragma unroll
        for (int j = 0; j < 8; j++) acc[i][j] = 0ULL;

    int buf = 0;
#pragma unroll 1
    for (int c = 0; c < 16; c++) {
        float4 wnext;
        if (c < 15) wnext = *(const float4*)(Wg + wrow*DD + (c+1)*8 + wkq);
        if (gemm_act) {
            const float* Wb = Ws + buf*2048;
#pragma unroll
            for (int kk = 0; kk < 8; kk++) {
                const int k = c*8 + kk;
                unsigned long long ap[4];
#pragma unroll
                for (int tp = 0; tp < 4; tp++)
                    ap[tp] = *(const unsigned long long*)&XsT[k*XST_LD + t0 + 2*tp];
                float4 w0 = *(const float4*)&Wb[kk*256 + n0];
                float4 w1 = *(const float4*)&Wb[kk*256 + n0 + 4];
                unsigned long long wp[8];
                wp[0] = pack2(w0.x); wp[1] = pack2(w0.y);
                wp[2] = pack2(w0.z); wp[3] = pack2(w0.w);
                wp[4] = pack2(w1.x); wp[5] = pack2(w1.y);
                wp[6] = pack2(w1.z); wp[7] = pack2(w1.w);
#pragma unroll
                for (int tp = 0; tp < 4; tp++)
#pragma unroll
                    for (int j = 0; j < 8; j++)
                        acc[tp][j] = fma2(ap[tp], wp[j], acc[tp][j]);
            }
        }
        if (c < 15) {
            float* Wb2 = Ws + (buf^1)*2048;
            Wb2[(wkq+0)*256 + wrow] = wnext.x;
            Wb2[(wkq+1)*256 + wrow] = wnext.y;
            Wb2[(wkq+2)*256 + wrow] = wnext.z;
            Wb2[(wkq+3)*256 + wrow] = wnext.w;
        }
        __syncthreads();
        buf ^= 1;
    }

    // epilogue: +bias, q -> Qs ; v -> Vs * head_en
    if (gemm_act) {
        const bool isv = (nn >= 16);
        const int d0 = (nn & 15) * 8;
        const float sc = isv ? head_en[h] : 1.0f;
        float* dst = isv ? Vs : Qs;
        float4 bia0 = *(const float4*)(wqkv_b + h*256 + n0);
        float4 bia1 = *(const float4*)(wqkv_b + h*256 + n0 + 4);
#pragma unroll
        for (int tp = 0; tp < 4; tp++) {
            float2 p[8];
#pragma unroll
            for (int j = 0; j < 8; j++) p[j] = unpack2(acc[tp][j]);
            int ta = t0 + 2*tp;
            int tb = ta + 1;
            if (ta < TT_) {
                float4 oa0, oa1;
                oa0.x = (p[0].x + bia0.x)*sc;  oa0.y = (p[1].x + bia0.y)*sc;
                oa0.z = (p[2].x + bia0.z)*sc;  oa0.w = (p[3].x + bia0.w)*sc;
                oa1.x = (p[4].x + bia1.x)*sc;  oa1.y = (p[5].x + bia1.y)*sc;
                oa1.z = (p[6].x + bia1.z)*sc;  oa1.w = (p[7].x + bia1.w)*sc;
                *(float4*)&dst[ta*DD + d0]     = oa0;
                *(float4*)&dst[ta*DD + d0 + 4] = oa1;
            }
            if (tb < TT_) {
                float4 ob0, ob1;
                ob0.x = (p[0].y + bia0.x)*sc;  ob0.y = (p[1].y + bia0.y)*sc;
                ob0.z = (p[2].y + bia0.z)*sc;  ob0.w = (p[3].y + bia0.w)*sc;
                ob1.x = (p[4].y + bia1.x)*sc;  ob1.y = (p[5].y + bia1.y)*sc;
                ob1.z = (p[6].y + bia1.z)*sc;  ob1.w = (p[7].y + bia1.w)*sc;
                *(float4*)&dst[tb*DD + d0]     = ob0;
                *(float4*)&dst[tb*DD + d0 + 4] = ob1;
            }
        }
    }
    __syncthreads();

    // ---------------- P2: scores (+ msk prefetch by warps 14/15) ----------------
    const float scale = 0.08838834764831843f;   // 1/sqrt(128)
    if (tid >= 448) {
        const float* mg = msk + (size_t)h * TT_ * TT_;
        for (int i = tid - 448; i < TT_*TT_; i += 64) Msk[i] = mg[i];
    } else if (tid < 441) {
        const int t0s = (tid / 21) * 4;
        const int s0 = (tid % 21) * 4;
        int ti[4];
#pragma unroll
        for (int i = 0; i < 4; i++) ti[i] = min(t0s + i, TT_ - 1);

        unsigned long long sacc[4][4];
#pragma unroll
        for (int i = 0; i < 4; i++)
#pragma unroll
            for (int j = 0; j < 4; j++) sacc[i][j] = 0ULL;

#pragma unroll 1
        for (int d = 0; d < DD; d += 4) {
            const int dp = d >> 1;
            ulonglong2 q[4];
#pragma unroll
            for (int i = 0; i < 4; i++)
                q[i] = *(const ulonglong2*)&Qs[ti[i]*DD + d];
            ulonglong2 ka = *(const ulonglong2*)&KT[(dp  )*168 + s0*2];
            ulonglong2 kb = *(const ulonglong2*)&KT[(dp  )*168 + s0*2 + 4];
            ulonglong2 kc = *(const ulonglong2*)&KT[(dp+1)*168 + s0*2];
            ulonglong2 kd = *(const ulonglong2*)&KT[(dp+1)*168 + s0*2 + 4];
#pragma unroll
            for (int i = 0; i < 4; i++) {
                unsigned long long u;
                u = add2(q[i].x, ka.x) & ABS2MASK;  sacc[i][0] = add2(sacc[i][0], u);
                u = add2(q[i].y, kc.x) & ABS2MASK;  sacc[i][0] = add2(sacc[i][0], u);
                u = add2(q[i].x, ka.y) & ABS2MASK;  sacc[i][1] = add2(sacc[i][1], u);
                u = add2(q[i].y, kc.y) & ABS2MASK;  sacc[i][1] = add2(sacc[i][1], u);
                u = add2(q[i].x, kb.x) & ABS2MASK;  sacc[i][2] = add2(sacc[i][2], u);
                u = add2(q[i].y, kd.x) & ABS2MASK;  sacc[i][2] = add2(sacc[i][2], u);
                u = add2(q[i].x, kb.y) & ABS2MASK;  sacc[i][3] = add2(sacc[i][3], u);
                u = add2(q[i].y, kd.y) & ABS2MASK;  sacc[i][3] = add2(sacc[i][3], u);
            }
        }
#pragma unroll
        for (int i = 0; i < 4; i++) {
            if (t0s + i >= TT_) continue;
#pragma unroll
            for (int j = 0; j < 4; j++) {
                if (s0 + j >= TT_) continue;
                float2 f = unpack2(sacc[i][j]);
                S[(s0 + j)*LDS_S + (t0s + i)] = -(f.x + f.y) * scale;
            }
        }
    }
    __syncthreads();

    // ---------------- P3: softmax over s (quad-parallel per t) ----------------
    if (tid < 352) {
        const int t  = tid >> 2;
        const int l4 = tid & 3;
        const bool valid = (t < TT_);
        const int sBeg = l4 * 21;
        const int sEnd = valid ? min(sBeg + 21, TT_) : sBeg;

        float mx = -1e30f;
        for (int s = sBeg; s < sEnd; s++) mx = fmaxf(mx, S[s*LDS_S + t]);
        mx = fmaxf(mx, __shfl_xor_sync(0xFFFFFFFFu, mx, 1));
        mx = fmaxf(mx, __shfl_xor_sync(0xFFFFFFFFu, mx, 2));

        float sum = 0.f;
        for (int s = sBeg; s < sEnd; s++) {
            float e = __expf(S[s*LDS_S + t] - mx);
            sum += e;
            S[s*LDS_S + t] = e;
        }
        sum += __shfl_xor_sync(0xFFFFFFFFu, sum, 1);
        sum += __shfl_xor_sync(0xFFFFFFFFu, sum, 2);
        float inv = 1.f / sum;

        for (int s = sBeg; s < sEnd; s++) {
            float mval = Msk[t*TT_ + s];
            float a = S[s*LDS_S + t] * inv * mval;
            S[s*LDS_S + t] = a;
            if (b == 0)
                ap_out[((size_t)t*TT_ + s)*HH + h] = a - 1.f + mval;
        }
    }
    __syncthreads();

    // ---------------- P4: AV GEMM -> g_bo ----------------
    float* bo = g_bo + (((size_t)b*HH + h)*TT_)*DD;
    if (tid < 336) {                      // 21 t-tiles x 16 d-tiles
        int t0a = (tid >> 4) * 4;
        int d0 = (tid & 15) * 8;
        unsigned long long av[4][4];
#pragma unroll
        for (int i = 0; i < 4; i++)
#pragma unroll
            for (int j = 0; j < 4; j++) av[i][j] = 0ULL;

#pragma unroll 2
        for (int s = 0; s < TT_; s++) {
            float4 a4 = *(const float4*)&S[s*LDS_S + t0a];
            ulonglong2 v0 = *(const ulonglong2*)&Vs[s*DD + d0];
            ulonglong2 v1 = *(const ulonglong2*)&Vs[s*DD + d0 + 4];
            unsigned long long a0 = pack2(a4.x);
            unsigned long long a1 = pack2(a4.y);
            unsigned long long a2v = pack2(a4.z);
            unsigned long long a3 = pack2(a4.w);
            av[0][0] = fma2(a0, v0.x, av[0][0]);
            av[0][1] = fma2(a0, v0.y, av[0][1]);
            av[0][2] = fma2(a0, v1.x, av[0][2]);
            av[0][3] = fma2(a0, v1.y, av[0][3]);
            av[1][0] = fma2(a1, v0.x, av[1][0]);
            av[1][1] = fma2(a1, v0.y, av[1][1]);
            av[1][2] = fma2(a1, v1.x, av[1][2]);
            av[1][3] = fma2(a1, v1.y, av[1][3]);
            av[2][0] = fma2(a2v, v0.x, av[2][0]);
            av[2][1] = fma2(a2v, v0.y, av[2][1]);
            av[2][2] = fma2(a2v, v1.x, av[2][2]);
            av[2][3] = fma2(a2v, v1.y, av[2][3]);
            av[3][0] = fma2(a3, v0.x, av[3][0]);
            av[3][1] = fma2(a3, v0.y, av[3][1]);
            av[3][2] = fma2(a3, v1.x, av[3][2]);
            av[3][3] = fma2(a3, v1.y, av[3][3]);
        }
#pragma unroll
        for (int i = 0; i < 4; i++) {
            int t = t0a + i;
            if (t >= TT_) continue;
            float2 p0 = unpack2(av[i][0]);
            float2 p1 = unpack2(av[i][1]);
            float2 p2 = unpack2(av[i][2]);
            float2 p3 = unpack2(av[i][3]);
            *(float4*)&bo[(size_t)t*DD + d0]     = make_float4(p0.x, p0.y, p1.x, p1.y);
            *(float4*)&bo[(size_t)t*DD + d0 + 4] = make_float4(p2.x, p2.y, p3.x, p3.y);
        }
    }
}

// ---------------------------------------------------------------------------
// Kernel 2a (R4-proven): G[m][d] = qgelu(sum_h bo)
// ---------------------------------------------------------------------------
__device__ __forceinline__ float qgelu4(float s) {
    float u = s + 4.f;
    return u / (1.f + __expf(-1.702f * u)) - 4.f;
}

__global__ void __launch_bounds__(128) reduce_gelu_kernel() {
    int idx = blockIdx.x * 128 + threadIdx.x;   // 0..41471
    int m  = idx >> 5;
    int kq = idx & 31;
    int bb = m / TT_, t = m - bb * TT_;
    const float4* base = (const float4*)g_bo + ((size_t)(bb*HH)*TT_ + t)*32 + kq;
    float s0 = 0.f, s1 = 0.f, s2 = 0.f, s3 = 0.f;
#pragma unroll
    for (int hh = 0; hh < HH; hh++) {
        float4 v = base[(size_t)hh*TT_*32];
        s0 += v.x; s1 += v.y; s2 += v.z; s3 += v.w;
    }
    float4 g;
    g.x = qgelu4(s0); g.y = qgelu4(s1); g.z = qgelu4(s2); g.w = qgelu4(s3);
    ((float4*)g_G)[(size_t)m*32 + kq] = g;
}

// ---------------------------------------------------------------------------
// Kernel 2b (R4-proven): out = x + G@Wf^T + bf.  162 blocks (16m x 64n).
// ---------------------------------------------------------------------------
__global__ void __launch_bounds__(256) fanout_kernel(const float* __restrict__ x,
                                                     const float* __restrict__ Wf,
                                                     const float* __restrict__ bf,
                                                     float* __restrict__ out) {
    extern __shared__ float sm[];
    float* Ws = sm;                 // [128][64]  Ws[k][n]
    float* Gs = sm + 128*64;        // [128][17]  Gs[k*17 + m]
    const int LDG_ = 17;
    const int mtile = blockIdx.x >> 1;
    const int half  = blockIdx.x & 1;
    const int m0 = mtile * 16;
    const int nbase = half * 64;
    const int tid = threadIdx.x;

    {
        int n  = tid & 63;
        int k4 = tid >> 6;              // 0..3
        const float* wr = Wf + (size_t)(nbase + n) * DD;
#pragma unroll
        for (int p = 0; p < 8; p++) {
            int kq = p * 4 + k4;        // 0..31
            float4 w = *(const float4*)(wr + kq * 4);
            Ws[(kq*4+0)*64 + n] = w.x;
            Ws[(kq*4+1)*64 + n] = w.y;
            Ws[(kq*4+2)*64 + n] = w.z;
            Ws[(kq*4+3)*64 + n] = w.w;
        }
    }
    {
#pragma unroll
        for (int p = 0; p < 2; p++) {
            int i  = p * 256 + tid;     // 0..511
            int ml = i >> 5;
            int kq = i & 31;
            float4 g = ((const float4*)g_G)[(size_t)(m0 + ml)*32 + kq];
            Gs[(kq*4+0)*LDG_ + ml] = g.x;
            Gs[(kq*4+1)*LDG_ + ml] = g.y;
            Gs[(kq*4+2)*LDG_ + ml] = g.z;
            Gs[(kq*4+3)*LDG_ + ml] = g.w;
        }
    }
    __syncthreads();

    const int m_ = tid >> 4;            // 0..15
    const int n0 = (tid & 15) * 4;      // 0..60
    float a0 = 0.f, a1 = 0.f, a2 = 0.f, a3 = 0.f;
#pragma unroll 8
    for (int k = 0; k < 128; k++) {
        float g = Gs[k*LDG_ + m_];
        float4 w = *(const float4*)&Ws[k*64 + n0];
        a0 += g * w.x; a1 += g * w.y; a2 += g * w.z; a3 += g * w.w;
    }
    int m = m0 + m_;
    int ng = nbase + n0;
    float4 xv = *(const float4*)&x[(size_t)m*DD + ng];
    float4 bv = *(const float4*)&bf[ng];
    float4 o;
    o.x = xv.x + a0 + bv.x;
    o.y = xv.y + a1 + bv.y;
    o.z = xv.z + a2 + bv.z;
    o.w = xv.w + a3 + bv.w;
    *(float4*)&out[(size_t)m*DD + ng] = o;
}

// ---------------------------------------------------------------------------
extern "C" void kernel_launch(void* const* d_in, const int* in_sizes, int n_in,
                              void* d_out, int out_size) {
    const float* x        = (const float*)d_in[0];
    const float* msk      = (const float*)d_in[1];
    const float* wqkv_w   = (const float*)d_in[2];
    const float* wqkv_b   = (const float*)d_in[3];
    const float* wk_w     = (const float*)d_in[4];
    const float* fanout_w = (const float*)d_in[5];
    const float* fanout_b = (const float*)d_in[6];
    const float* head_en  = (const float*)d_in[7];

    float* out = (float*)d_out;
    float* ap_out = out + (size_t)BT * DD;   // 165888 onward

    const int smemA = SMEM_FLOATS * 4;                   // 215632
    const int smemF = (128*64 + 128*17) * 4 + 16;        // ~41.5KB

    cudaFuncSetAttribute(attn_fused,    cudaFuncAttributeMaxDynamicSharedMemorySize, smemA);
    cudaFuncSetAttribute(fanout_kernel, cudaFuncAttributeMaxDynamicSharedMemorySize, smemF);

    attn_fused<<<BB * HH, 512, smemA>>>(x, wqkv_w, wqkv_b, wk_w, msk, head_en, ap_out);

    reduce_gelu_kernel<<<324, 128>>>();

    fanout_kernel<<<162, 256, smemF>>>(x, fanout_w, fanout_b, out);
}

// round 12
// speedup vs baseline: 1.3218x; 1.1372x over previous
#include <cuda_runtime.h>
#include <cuda_bf16.h>
#include <math.h>
#include <stdint.h>

#define BB 16
#define TT_ 81
#define DD 128
#define HH 8
#define BT (BB*TT_)       // 1296

__device__ float g_bo[BB*HH*TT_*DD];
__device__ float g_G[BT*DD];

// ---------------- packed fp32x2 helpers ----------------
static __device__ __forceinline__ unsigned long long add2(unsigned long long a,
                                                          unsigned long long b) {
    unsigned long long r;
    asm("add.rn.f32x2 %0, %1, %2;" : "=l"(r) : "l"(a), "l"(b));
    return r;
}
static __device__ __forceinline__ unsigned long long fma2(unsigned long long a,
                                                          unsigned long long b,
                                                          unsigned long long c) {
    unsigned long long r;
    asm("fma.rn.f32x2 %0, %1, %2, %3;" : "=l"(r) : "l"(a), "l"(b), "l"(c));
    return r;
}
static __device__ __forceinline__ unsigned long long pack2(float x) {
    unsigned long long r;
    asm("mov.b64 %0, {%1, %1};" : "=l"(r) : "f"(x));
    return r;
}
static __device__ __forceinline__ float2 unpack2(unsigned long long v) {
    float2 f;
    asm("mov.b64 {%0, %1}, %2;" : "=f"(f.x), "=f"(f.y) : "l"(v));
    return f;
}
#define ABS2MASK 0x7FFFFFFF7FFFFFFFULL

static __device__ __forceinline__ uint32_t smem_to_u32(const void* p) {
    uint32_t a;
    asm("{ .reg .u64 t; cvta.to.shared.u64 t, %1; cvt.u32.u64 %0, t; }" : "=r"(a) : "l"(p));
    return a;
}
#define LDMX4(r0, r1, r2, r3, addr) \
    asm volatile("ldmatrix.sync.aligned.m8n8.x4.shared.b16 {%0,%1,%2,%3}, [%4];" \
        : "=r"(r0), "=r"(r1), "=r"(r2), "=r"(r3) : "r"(addr))
#define MMA16816(c, a0, a1, a2, a3, b0, b1) \
    asm volatile("mma.sync.aligned.m16n8k16.row.col.f32.bf16.bf16.f32 " \
        "{%0,%1,%2,%3}, {%4,%5,%6,%7}, {%8,%9}, {%0,%1,%2,%3};" \
        : "+f"((c)[0]), "+f"((c)[1]), "+f"((c)[2]), "+f"((c)[3]) \
        : "r"(a0), "r"(a1), "r"(a2), "r"(a3), "r"(b0), "r"(b1))

// split 8 floats -> bf16-hi uint4 + bf16-lo uint4
static __device__ __forceinline__ void split8(float4 a, float4 b, uint4& hi, uint4& lo) {
    float va[8] = {a.x, a.y, a.z, a.w, b.x, b.y, b.z, b.w};
    unsigned short h[8], l[8];
#pragma unroll
    for (int i = 0; i < 8; i++) {
        __nv_bfloat16 bh = __float2bfloat16(va[i]);
        h[i] = __bfloat16_as_ushort(bh);
        l[i] = __bfloat16_as_ushort(__float2bfloat16(va[i] - __bfloat162float(bh)));
    }
    hi = make_uint4((uint32_t)h[0]|((uint32_t)h[1]<<16), (uint32_t)h[2]|((uint32_t)h[3]<<16),
                    (uint32_t)h[4]|((uint32_t)h[5]<<16), (uint32_t)h[6]|((uint32_t)h[7]<<16));
    lo = make_uint4((uint32_t)l[0]|((uint32_t)l[1]<<16), (uint32_t)l[2]|((uint32_t)l[3]<<16),
                    (uint32_t)l[4]|((uint32_t)l[5]<<16), (uint32_t)l[6]|((uint32_t)l[7]<<16));
}

// ---- smem layout ----
// bytes: Ahi[96][136]bf16 @0 (26112), Alo @26112, W[256][136]bf16 @52224 (69632)
// overlays after GEMM: Qs f32 [81][132] @0, Vs f32 [81][132] @52224
#define AHI_B   0
#define ALO_B   26112
#define WB_B    52224
#define VS_F    13056
#define KT_F    30464            // byte 121856, 64 dp x 168 fl
#define LDS_S   84
#define S_F     41216            // byte 164864
#define MSK_F   48020            // byte 192080
#define BIAS_F  54584            // byte 218336
#define SMEM_FLOATS (BIAS_F + 256)   // 54840 fl = 219360 B
#define QV_LD   132

__global__ void __launch_bounds__(512, 1)
attn_mma(const float* __restrict__ x,
         const float* __restrict__ wqkv_w,
         const float* __restrict__ wqkv_b,
         const float* __restrict__ wk_w,
         const float* __restrict__ msk,
         const float* __restrict__ head_en,
         float* __restrict__ ap_out) {
    extern __shared__ float sm[];
    char* smb = (char*)sm;
    const uint32_t sb = smem_to_u32(sm);
    float* Qs  = sm;                 // stride 132, overlays A after GEMM
    float* Vs  = sm + VS_F;          // stride 132, overlays W after GEMM
    float* KT  = sm + KT_F;
    float* S   = sm + S_F;
    float* Msk = sm + MSK_F;
    float* BiasS = sm + BIAS_F;

    const int b = blockIdx.x >> 3;
    const int h = blockIdx.x & 7;
    const int tid = threadIdx.x;
    const int wid = tid >> 5;
    const int lane = tid & 31;

    const float* xb = x + (size_t)b * TT_ * DD;
    const float* Wg = wqkv_w + ((size_t)h * 2 * DD) * DD;   // 256 x 128

    // ---------------- S1: stage A hi/lo, W hi, bias, KT, S, Msk ----------------
    for (int idx = tid; idx < 96 * 16; idx += 512) {        // A: (t, k8)
        int t = idx >> 4, k0 = (idx & 15) << 3;
        uint4 hi = make_uint4(0, 0, 0, 0), lo = make_uint4(0, 0, 0, 0);
        if (t < TT_) {
            float4 va = *(const float4*)(xb + t * DD + k0);
            float4 vb = *(const float4*)(xb + t * DD + k0 + 4);
            split8(va, vb, hi, lo);
        }
        uint32_t off = (uint32_t)t * 272 + (uint32_t)k0 * 2;
        *(uint4*)(smb + AHI_B + off) = hi;
        *(uint4*)(smb + ALO_B + off) = lo;
    }
    for (int idx = tid; idx < 256 * 16; idx += 512) {       // W hi: (n, k8)
        int n = idx >> 4, k0 = (idx & 15) << 3;
        float4 va = *(const float4*)(Wg + (size_t)n * DD + k0);
        float4 vb = *(const float4*)(Wg + (size_t)n * DD + k0 + 4);
        uint4 hi, lo;
        split8(va, vb, hi, lo);
        *(uint4*)(smb + WB_B + (uint32_t)n * 272 + (uint32_t)k0 * 2) = hi;
    }
    if (tid < 256) BiasS[tid] = wqkv_b[h * 256 + tid];
    {   // KT (negated k), S zero, Msk
        const float4* x4  = (const float4*)xb;
        const float4* wk4 = (const float4*)(wk_w + h * DD);
        for (int i = tid; i < 32 * TT_; i += 512) {
            int dq = i / TT_, t = i - dq * TT_;
            float4 xv = x4[t * 32 + dq];
            float4 wv = wk4[dq];
            int dp = dq * 2;
            *(float2*)&KT[(dp    ) * 168 + t * 2] = make_float2(-(xv.x*wv.x), -(xv.y*wv.y));
            *(float2*)&KT[(dp + 1) * 168 + t * 2] = make_float2(-(xv.z*wv.z), -(xv.w*wv.w));
        }
        for (int i = tid; i < 192; i += 512) {
            int dp = i / 3, s = 81 + (i % 3);
            *(float2*)&KT[dp * 168 + s * 2] = make_float2(0.f, 0.f);
        }
        const float4 z4 = make_float4(0.f, 0.f, 0.f, 0.f);
        for (int i = tid; i < TT_ * LDS_S / 4; i += 512) ((float4*)S)[i] = z4;
        const float* mg = msk + (size_t)h * TT_ * TT_;
        for (int i = tid; i < TT_ * TT_; i += 512) Msk[i] = mg[i];
    }
    __syncthreads();

    // ---------------- GEMM: 16 warps x (3 m16 x 4 n8) ----------------
    const int mgrp = wid >> 3, ngrp = wid & 7;
    const int mb = mgrp * 48, nb = ngrp * 32;
    const int j = lane >> 3, lr = lane & 7;
    const uint32_t aOff = (uint32_t)(mb + ((j & 1) << 3) + lr) * 272 + ((uint32_t)(j >> 1) << 4);
    const uint32_t bOff = (uint32_t)(nb + ((j >> 1) << 3) + lr) * 272 + ((uint32_t)(j & 1) << 4);
    const uint32_t aHi = sb + AHI_B + aOff;
    const uint32_t aLo = sb + ALO_B + aOff;
    const uint32_t bBs = sb + WB_B + bOff;

    float acc[3][4][4];
#pragma unroll
    for (int m = 0; m < 3; m++)
#pragma unroll
        for (int n = 0; n < 4; n++)
#pragma unroll
            for (int q = 0; q < 4; q++) acc[m][n][q] = 0.f;

#pragma unroll 1
    for (int pass = 0; pass < 3; pass++) {
        if (pass == 2) {
            __syncthreads();                    // all reads of W-hi done
            for (int idx = tid; idx < 256 * 16; idx += 512) {
                int n = idx >> 4, k0 = (idx & 15) << 3;
                float4 va = *(const float4*)(Wg + (size_t)n * DD + k0);
                float4 vb = *(const float4*)(Wg + (size_t)n * DD + k0 + 4);
                uint4 hi, lo;
                split8(va, vb, hi, lo);
                *(uint4*)(smb + WB_B + (uint32_t)n * 272 + (uint32_t)k0 * 2) = lo;
            }
            __syncthreads();
        }
        const uint32_t aB = (pass == 1) ? aLo : aHi;
#pragma unroll
        for (int ks = 0; ks < 8; ks++) {
            const uint32_t ko = (uint32_t)ks * 32;
            uint32_t ar[3][4], br[2][4];
#pragma unroll
            for (int mt = 0; mt < 3; mt++)
                LDMX4(ar[mt][0], ar[mt][1], ar[mt][2], ar[mt][3],
                      aB + (uint32_t)mt * (16 * 272) + ko);
#pragma unroll
            for (int hf = 0; hf < 2; hf++)
                LDMX4(br[hf][0], br[hf][1], br[hf][2], br[hf][3],
                      bBs + (uint32_t)hf * (16 * 272) + ko);
#pragma unroll
            for (int mt = 0; mt < 3; mt++)
#pragma unroll
                for (int ns = 0; ns < 4; ns++) {
                    const int hf = ns >> 1, pr = (ns & 1) * 2;
                    MMA16816(acc[mt][ns], ar[mt][0], ar[mt][1], ar[mt][2], ar[mt][3],
                             br[hf][pr], br[hf][pr + 1]);
                }
        }
    }
    __syncthreads();    // all ldmatrix reads done before Qs/Vs overlay

    // epilogue: +bias; n<128 -> Qs, n>=128 -> Vs * head_en
    {
        const float he = head_en[h];
        const int r0 = (lane >> 2);
        const int cc = 2 * (lane & 3);
#pragma unroll
        for (int mt = 0; mt < 3; mt++) {
            int ta = mb + mt * 16 + r0;
            int tb2 = ta + 8;
#pragma unroll
            for (int ns = 0; ns < 4; ns++) {
                int n = nb + ns * 8 + cc;
                bool isv = (n >= 128);
                float* dst = isv ? Vs : Qs;
                int col = isv ? n - 128 : n;
                float scl = isv ? he : 1.f;
                float b0 = BiasS[n], b1 = BiasS[n + 1];
                if (ta < TT_) {
                    float2 o = make_float2((acc[mt][ns][0] + b0) * scl,
                                           (acc[mt][ns][1] + b1) * scl);
                    *(float2*)&dst[ta * QV_LD + col] = o;
                }
                if (tb2 < TT_) {
                    float2 o = make_float2((acc[mt][ns][2] + b0) * scl,
                                           (acc[mt][ns][3] + b1) * scl);
                    *(float2*)&dst[tb2 * QV_LD + col] = o;
                }
            }
        }
    }
    __syncthreads();

    // ---------------- P2: scores ----------------
    const float scale = 0.08838834764831843f;
    if (tid < 441) {
        const int t0s = (tid / 21) * 4;
        const int s0 = (tid % 21) * 4;
        int ti[4];
#pragma unroll
        for (int i = 0; i < 4; i++) ti[i] = min(t0s + i, TT_ - 1);
        unsigned long long sacc[4][4];
#pragma unroll
        for (int i = 0; i < 4; i++)
#pragma unroll
            for (int q = 0; q < 4; q++) sacc[i][q] = 0ULL;
#pragma unroll 1
        for (int d = 0; d < DD; d += 4) {
            const int dp = d >> 1;
            ulonglong2 q[4];
#pragma unroll
            for (int i = 0; i < 4; i++)
                q[i] = *(const ulonglong2*)&Qs[ti[i] * QV_LD + d];
            ulonglong2 ka = *(const ulonglong2*)&KT[(dp    ) * 168 + s0 * 2];
            ulonglong2 kb = *(const ulonglong2*)&KT[(dp    ) * 168 + s0 * 2 + 4];
            ulonglong2 kc = *(const ulonglong2*)&KT[(dp + 1) * 168 + s0 * 2];
            ulonglong2 kd = *(const ulonglong2*)&KT[(dp + 1) * 168 + s0 * 2 + 4];
#pragma unroll
            for (int i = 0; i < 4; i++) {
                unsigned long long u;
                u = add2(q[i].x, ka.x) & ABS2MASK;  sacc[i][0] = add2(sacc[i][0], u);
                u = add2(q[i].y, kc.x) & ABS2MASK;  sacc[i][0] = add2(sacc[i][0], u);
                u = add2(q[i].x, ka.y) & ABS2MASK;  sacc[i][1] = add2(sacc[i][1], u);
                u = add2(q[i].y, kc.y) & ABS2MASK;  sacc[i][1] = add2(sacc[i][1], u);
                u = add2(q[i].x, kb.x) & ABS2MASK;  sacc[i][2] = add2(sacc[i][2], u);
                u = add2(q[i].y, kd.x) & ABS2MASK;  sacc[i][2] = add2(sacc[i][2], u);
                u = add2(q[i].x, kb.y) & ABS2MASK;  sacc[i][3] = add2(sacc[i][3], u);
                u = add2(q[i].y, kd.y) & ABS2MASK;  sacc[i][3] = add2(sacc[i][3], u);
            }
        }
#pragma unroll
        for (int i = 0; i < 4; i++) {
            if (t0s + i >= TT_) continue;
#pragma unroll
            for (int q = 0; q < 4; q++) {
                if (s0 + q >= TT_) continue;
                float2 f = unpack2(sacc[i][q]);
                S[(s0 + q) * LDS_S + (t0s + i)] = -(f.x + f.y) * scale;
            }
        }
    }
    __syncthreads();

    // ---------------- P3: softmax over s ----------------
    if (tid < 352) {
        const int t  = tid >> 2;
        const int l4 = tid & 3;
        const bool valid = (t < TT_);
        const int sBeg = l4 * 21;
        const int sEnd = valid ? min(sBeg + 21, TT_) : sBeg;
        float mx = -1e30f;
        for (int s = sBeg; s < sEnd; s++) mx = fmaxf(mx, S[s * LDS_S + t]);
        mx = fmaxf(mx, __shfl_xor_sync(0xFFFFFFFFu, mx, 1));
        mx = fmaxf(mx, __shfl_xor_sync(0xFFFFFFFFu, mx, 2));
        float sum = 0.f;
        for (int s = sBeg; s < sEnd; s++) {
            float e = __expf(S[s * LDS_S + t] - mx);
            sum += e;
            S[s * LDS_S + t] = e;
        }
        sum += __shfl_xor_sync(0xFFFFFFFFu, sum, 1);
        sum += __shfl_xor_sync(0xFFFFFFFFu, sum, 2);
        float inv = 1.f / sum;
        for (int s = sBeg; s < sEnd; s++) {
            float mval = Msk[t * TT_ + s];
            float a = S[s * LDS_S + t] * inv * mval;
            S[s * LDS_S + t] = a;
            if (b == 0)
                ap_out[((size_t)t * TT_ + s) * HH + h] = a - 1.f + mval;
        }
    }
    __syncthreads();

    // ---------------- P4: AV -> g_bo ----------------
    float* bo = g_bo + (((size_t)b * HH + h) * TT_) * DD;
    if (tid < 336) {
        int t0a = (tid >> 4) * 4;
        int d0 = (tid & 15) * 8;
        unsigned long long av[4][4];
#pragma unroll
        for (int i = 0; i < 4; i++)
#pragma unroll
            for (int q = 0; q < 4; q++) av[i][q] = 0ULL;
#pragma unroll 2
        for (int s = 0; s < TT_; s++) {
            float4 a4 = *(const float4*)&S[s * LDS_S + t0a];
            ulonglong2 v0 = *(const ulonglong2*)&Vs[s * QV_LD + d0];
            ulonglong2 v1 = *(const ulonglong2*)&Vs[s * QV_LD + d0 + 4];
            unsigned long long p0 = pack2(a4.x), p1 = pack2(a4.y);
            unsigned long long p2 = pack2(a4.z), p3 = pack2(a4.w);
            av[0][0] = fma2(p0, v0.x, av[0][0]);  av[0][1] = fma2(p0, v0.y, av[0][1]);
            av[0][2] = fma2(p0, v1.x, av[0][2]);  av[0][3] = fma2(p0, v1.y, av[0][3]);
            av[1][0] = fma2(p1, v0.x, av[1][0]);  av[1][1] = fma2(p1, v0.y, av[1][1]);
            av[1][2] = fma2(p1, v1.x, av[1][2]);  av[1][3] = fma2(p1, v1.y, av[1][3]);
            av[2][0] = fma2(p2, v0.x, av[2][0]);  av[2][1] = fma2(p2, v0.y, av[2][1]);
            av[2][2] = fma2(p2, v1.x, av[2][2]);  av[2][3] = fma2(p2, v1.y, av[2][3]);
            av[3][0] = fma2(p3, v0.x, av[3][0]);  av[3][1] = fma2(p3, v0.y, av[3][1]);
            av[3][2] = fma2(p3, v1.x, av[3][2]);  av[3][3] = fma2(p3, v1.y, av[3][3]);
        }
#pragma unroll
        for (int i = 0; i < 4; i++) {
            int t = t0a + i;
            if (t >= TT_) continue;
            float2 q0 = unpack2(av[i][0]), q1 = unpack2(av[i][1]);
            float2 q2 = unpack2(av[i][2]), q3 = unpack2(av[i][3]);
            *(float4*)&bo[(size_t)t * DD + d0]     = make_float4(q0.x, q0.y, q1.x, q1.y);
            *(float4*)&bo[(size_t)t * DD + d0 + 4] = make_float4(q2.x, q2.y, q3.x, q3.y);
        }
    }
}

// ---------------------------------------------------------------------------
__device__ __forceinline__ float qgelu4(float s) {
    float u = s + 4.f;
    return u / (1.f + __expf(-1.702f * u)) - 4.f;
}

__global__ void __launch_bounds__(128) reduce_gelu_kernel() {
    int idx = blockIdx.x * 128 + threadIdx.x;
    int m  = idx >> 5, kq = idx & 31;
    int bb = m / TT_, t = m - bb * TT_;
    const float4* base = (const float4*)g_bo + ((size_t)(bb * HH) * TT_ + t) * 32 + kq;
    float s0 = 0.f, s1 = 0.f, s2 = 0.f, s3 = 0.f;
#pragma unroll
    for (int hh = 0; hh < HH; hh++) {
        float4 v = base[(size_t)hh * TT_ * 32];
        s0 += v.x; s1 += v.y; s2 += v.z; s3 += v.w;
    }
    float4 g;
    g.x = qgelu4(s0); g.y = qgelu4(s1); g.z = qgelu4(s2); g.w = qgelu4(s3);
    ((float4*)g_G)[(size_t)m * 32 + kq] = g;
}

__global__ void __launch_bounds__(256) fanout_kernel(const float* __restrict__ x,
                                                     const float* __restrict__ Wf,
                                                     const float* __restrict__ bf,
                                                     float* __restrict__ out) {
    extern __shared__ float sm[];
    float* Ws = sm;                 // [128][64]
    float* Gs = sm + 128 * 64;      // [128][17]
    const int LDG_ = 17;
    const int mtile = blockIdx.x >> 1;
    const int half  = blockIdx.x & 1;
    const int m0 = mtile * 16;
    const int nbase = half * 64;
    const int tid = threadIdx.x;
    {
        int n  = tid & 63, k4 = tid >> 6;
        const float* wr = Wf + (size_t)(nbase + n) * DD;
#pragma unroll
        for (int p = 0; p < 8; p++) {
            int kq = p * 4 + k4;
            float4 w = *(const float4*)(wr + kq * 4);
            Ws[(kq*4+0)*64 + n] = w.x;  Ws[(kq*4+1)*64 + n] = w.y;
            Ws[(kq*4+2)*64 + n] = w.z;  Ws[(kq*4+3)*64 + n] = w.w;
        }
    }
    {
#pragma unroll
        for (int p = 0; p < 2; p++) {
            int i  = p * 256 + tid;
            int ml = i >> 5, kq = i & 31;
            float4 g = ((const float4*)g_G)[(size_t)(m0 + ml) * 32 + kq];
            Gs[(kq*4+0)*LDG_ + ml] = g.x;  Gs[(kq*4+1)*LDG_ + ml] = g.y;
            Gs[(kq*4+2)*LDG_ + ml] = g.z;  Gs[(kq*4+3)*LDG_ + ml] = g.w;
        }
    }
    __syncthreads();
    const int m_ = tid >> 4;
    const int n0 = (tid & 15) * 4;
    float a0 = 0.f, a1 = 0.f, a2 = 0.f, a3 = 0.f;
#pragma unroll 8
    for (int k = 0; k < 128; k++) {
        float g = Gs[k * LDG_ + m_];
        float4 w = *(const float4*)&Ws[k * 64 + n0];
        a0 += g * w.x; a1 += g * w.y; a2 += g * w.z; a3 += g * w.w;
    }
    int m = m0 + m_, ng = nbase + n0;
    float4 xv = *(const float4*)&x[(size_t)m * DD + ng];
    float4 bv = *(const float4*)&bf[ng];
    *(float4*)&out[(size_t)m * DD + ng] =
        make_float4(xv.x + a0 + bv.x, xv.y + a1 + bv.y, xv.z + a2 + bv.z, xv.w + a3 + bv.w);
}

// ---------------------------------------------------------------------------
extern "C" void kernel_launch(void* const* d_in, const int* in_sizes, int n_in,
                              void* d_out, int out_size) {
    const float* x        = (const float*)d_in[0];
    const float* msk      = (const float*)d_in[1];
    const float* wqkv_w   = (const float*)d_in[2];
    const float* wqkv_b   = (const float*)d_in[3];
    const float* wk_w     = (const float*)d_in[4];
    const float* fanout_w = (const float*)d_in[5];
    const float* fanout_b = (const float*)d_in[6];
    const float* head_en  = (const float*)d_in[7];

    float* out = (float*)d_out;
    float* ap_out = out + (size_t)BT * DD;

    const int smemA = SMEM_FLOATS * 4;                   // 219360
    const int smemF = (128*64 + 128*17) * 4 + 16;

    cudaFuncSetAttribute(attn_mma,      cudaFuncAttributeMaxDynamicSharedMemorySize, smemA);
    cudaFuncSetAttribute(fanout_kernel, cudaFuncAttributeMaxDynamicSharedMemorySize, smemF);

    attn_mma<<<BB * HH, 512, smemA>>>(x, wqkv_w, wqkv_b, wk_w, msk, head_en, ap_out);

    reduce_gelu_kernel<<<324, 128>>>();

    fanout_kernel<<<162, 256, smemF>>>(x, fanout_w, fanout_b, out);
}

// round 13
// speedup vs baseline: 1.3953x; 1.0556x over previous
#include <cuda_runtime.h>
#include <cuda_bf16.h>
#include <math.h>
#include <stdint.h>

#define BB 16
#define TT_ 81
#define DD 128
#define HH 8
#define BT (BB*TT_)       // 1296

__device__ float g_bo[BB*HH*TT_*DD];
__device__ float g_G[BT*DD];

// ---------------- packed fp32x2 helpers ----------------
static __device__ __forceinline__ unsigned long long add2(unsigned long long a,
                                                          unsigned long long b) {
    unsigned long long r;
    asm("add.rn.f32x2 %0, %1, %2;" : "=l"(r) : "l"(a), "l"(b));
    return r;
}
static __device__ __forceinline__ unsigned long long fma2(unsigned long long a,
                                                          unsigned long long b,
                                                          unsigned long long c) {
    unsigned long long r;
    asm("fma.rn.f32x2 %0, %1, %2, %3;" : "=l"(r) : "l"(a), "l"(b), "l"(c));
    return r;
}
static __device__ __forceinline__ unsigned long long pack2(float x) {
    unsigned long long r;
    asm("mov.b64 %0, {%1, %1};" : "=l"(r) : "f"(x));
    return r;
}
static __device__ __forceinline__ float2 unpack2(unsigned long long v) {
    float2 f;
    asm("mov.b64 {%0, %1}, %2;" : "=f"(f.x), "=f"(f.y) : "l"(v));
    return f;
}
#define ABS2MASK 0x7FFFFFFF7FFFFFFFULL

static __device__ __forceinline__ uint32_t smem_to_u32(const void* p) {
    uint32_t a;
    asm("{ .reg .u64 t; cvta.to.shared.u64 t, %1; cvt.u32.u64 %0, t; }" : "=r"(a) : "l"(p));
    return a;
}
#define LDMX4(r0, r1, r2, r3, addr) \
    asm volatile("ldmatrix.sync.aligned.m8n8.x4.shared.b16 {%0,%1,%2,%3}, [%4];" \
        : "=r"(r0), "=r"(r1), "=r"(r2), "=r"(r3) : "r"(addr))
#define MMA16816(c, a0, a1, a2, a3, b0, b1) \
    asm volatile("mma.sync.aligned.m16n8k16.row.col.f32.bf16.bf16.f32 " \
        "{%0,%1,%2,%3}, {%4,%5,%6,%7}, {%8,%9}, {%0,%1,%2,%3};" \
        : "+f"((c)[0]), "+f"((c)[1]), "+f"((c)[2]), "+f"((c)[3]) \
        : "r"(a0), "r"(a1), "r"(a2), "r"(a3), "r"(b0), "r"(b1))

// split 8 floats -> bf16-hi uint4 + bf16-lo uint4
static __device__ __forceinline__ void split8(float4 a, float4 b, uint4& hi, uint4& lo) {
    float va[8] = {a.x, a.y, a.z, a.w, b.x, b.y, b.z, b.w};
    unsigned short h[8], l[8];
#pragma unroll
    for (int i = 0; i < 8; i++) {
        __nv_bfloat16 bh = __float2bfloat16(va[i]);
        h[i] = __bfloat16_as_ushort(bh);
        l[i] = __bfloat16_as_ushort(__float2bfloat16(va[i] - __bfloat162float(bh)));
    }
    hi = make_uint4((uint32_t)h[0]|((uint32_t)h[1]<<16), (uint32_t)h[2]|((uint32_t)h[3]<<16),
                    (uint32_t)h[4]|((uint32_t)h[5]<<16), (uint32_t)h[6]|((uint32_t)h[7]<<16));
    lo = make_uint4((uint32_t)l[0]|((uint32_t)l[1]<<16), (uint32_t)l[2]|((uint32_t)l[3]<<16),
                    (uint32_t)l[4]|((uint32_t)l[5]<<16), (uint32_t)l[6]|((uint32_t)l[7]<<16));
}
// cvt-only: 8 floats -> bf16-hi uint4
static __device__ __forceinline__ uint4 cvt8(float4 a, float4 b) {
    float va[8] = {a.x, a.y, a.z, a.w, b.x, b.y, b.z, b.w};
    unsigned short h[8];
#pragma unroll
    for (int i = 0; i < 8; i++) h[i] = __bfloat16_as_ushort(__float2bfloat16(va[i]));
    return make_uint4((uint32_t)h[0]|((uint32_t)h[1]<<16), (uint32_t)h[2]|((uint32_t)h[3]<<16),
                      (uint32_t)h[4]|((uint32_t)h[5]<<16), (uint32_t)h[6]|((uint32_t)h[7]<<16));
}

// ---- smem layout (same as R12) ----
#define AHI_B   0
#define ALO_B   26112
#define WB_B    52224
#define VS_F    13056
#define KT_F    30464
#define LDS_S   84
#define S_F     41216
#define MSK_F   48020
#define BIAS_F  54584
#define SMEM_FLOATS (BIAS_F + 256)   // 54840 fl = 219360 B
#define QV_LD   132

__global__ void __launch_bounds__(512, 1)
attn_mma(const float* __restrict__ x,
         const float* __restrict__ wqkv_w,
         const float* __restrict__ wqkv_b,
         const float* __restrict__ wk_w,
         const float* __restrict__ msk,
         const float* __restrict__ head_en,
         float* __restrict__ ap_out) {
    extern __shared__ float sm[];
    char* smb = (char*)sm;
    const uint32_t sb = smem_to_u32(sm);
    float* Qs  = sm;                 // stride 132, overlays A after GEMM
    float* Vs  = sm + VS_F;          // stride 132, overlays W after GEMM
    float* KT  = sm + KT_F;
    float* S   = sm + S_F;
    float* Msk = sm + MSK_F;
    float* BiasS = sm + BIAS_F;

    const int b = blockIdx.x >> 3;
    const int h = blockIdx.x & 7;
    const int tid = threadIdx.x;
    const int wid = tid >> 5;
    const int lane = tid & 31;

    const float* xb = x + (size_t)b * TT_ * DD;
    const float* Wg = wqkv_w + ((size_t)h * 2 * DD) * DD;   // 256 x 128

    // ---------------- S1: stage A hi/lo, W hi, bias, KT, S, Msk ----------------
    for (int idx = tid; idx < 96 * 16; idx += 512) {        // A: (t, k8)
        int t = idx >> 4, k0 = (idx & 15) << 3;
        uint4 hi = make_uint4(0, 0, 0, 0), lo = make_uint4(0, 0, 0, 0);
        if (t < TT_) {
            float4 va = *(const float4*)(xb + t * DD + k0);
            float4 vb = *(const float4*)(xb + t * DD + k0 + 4);
            split8(va, vb, hi, lo);
        }
        uint32_t off = (uint32_t)t * 272 + (uint32_t)k0 * 2;
        *(uint4*)(smb + AHI_B + off) = hi;
        *(uint4*)(smb + ALO_B + off) = lo;
    }
    for (int idx = tid; idx < 256 * 16; idx += 512) {       // W hi only: (n, k8)
        int n = idx >> 4, k0 = (idx & 15) << 3;
        float4 va = *(const float4*)(Wg + (size_t)n * DD + k0);
        float4 vb = *(const float4*)(Wg + (size_t)n * DD + k0 + 4);
        *(uint4*)(smb + WB_B + (uint32_t)n * 272 + (uint32_t)k0 * 2) = cvt8(va, vb);
    }
    if (tid < 256) BiasS[tid] = wqkv_b[h * 256 + tid];
    {   // KT (negated k), S zero, Msk
        const float4* x4  = (const float4*)xb;
        const float4* wk4 = (const float4*)(wk_w + h * DD);
        for (int i = tid; i < 32 * TT_; i += 512) {
            int dq = i / TT_, t = i - dq * TT_;
            float4 xv = x4[t * 32 + dq];
            float4 wv = wk4[dq];
            int dp = dq * 2;
            *(float2*)&KT[(dp    ) * 168 + t * 2] = make_float2(-(xv.x*wv.x), -(xv.y*wv.y));
            *(float2*)&KT[(dp + 1) * 168 + t * 2] = make_float2(-(xv.z*wv.z), -(xv.w*wv.w));
        }
        for (int i = tid; i < 192; i += 512) {
            int dp = i / 3, s = 81 + (i % 3);
            *(float2*)&KT[dp * 168 + s * 2] = make_float2(0.f, 0.f);
        }
        const float4 z4 = make_float4(0.f, 0.f, 0.f, 0.f);
        for (int i = tid; i < TT_ * LDS_S / 4; i += 512) ((float4*)S)[i] = z4;
        const float* mg = msk + (size_t)h * TT_ * TT_;
        for (int i = tid; i < TT_ * TT_; i += 512) Msk[i] = mg[i];
    }
    __syncthreads();

    // ---------------- GEMM: 16 warps x (3 m16 x 4 n8), 2 passes ----------------
    const int mgrp = wid >> 3, ngrp = wid & 7;
    const int mb = mgrp * 48, nb = ngrp * 32;
    const int j = lane >> 3, lr = lane & 7;
    const uint32_t aOff = (uint32_t)(mb + ((j & 1) << 3) + lr) * 272 + ((uint32_t)(j >> 1) << 4);
    const uint32_t bOff = (uint32_t)(nb + ((j >> 1) << 3) + lr) * 272 + ((uint32_t)(j & 1) << 4);
    const uint32_t aHi = sb + AHI_B + aOff;
    const uint32_t aLo = sb + ALO_B + aOff;
    const uint32_t bBs = sb + WB_B + bOff;

    float acc[3][4][4];
#pragma unroll
    for (int m = 0; m < 3; m++)
#pragma unroll
        for (int n = 0; n < 4; n++)
#pragma unroll
            for (int q = 0; q < 4; q++) acc[m][n][q] = 0.f;

#pragma unroll
    for (int pass = 0; pass < 2; pass++) {
        const uint32_t aB = (pass == 1) ? aLo : aHi;
#pragma unroll
        for (int ks = 0; ks < 8; ks++) {
            const uint32_t ko = (uint32_t)ks * 32;
            uint32_t ar[3][4], br[2][4];
#pragma unroll
            for (int mt = 0; mt < 3; mt++)
                LDMX4(ar[mt][0], ar[mt][1], ar[mt][2], ar[mt][3],
                      aB + (uint32_t)mt * (16 * 272) + ko);
#pragma unroll
            for (int hf = 0; hf < 2; hf++)
                LDMX4(br[hf][0], br[hf][1], br[hf][2], br[hf][3],
                      bBs + (uint32_t)hf * (16 * 272) + ko);
#pragma unroll
            for (int mt = 0; mt < 3; mt++)
#pragma unroll
                for (int ns = 0; ns < 4; ns++) {
                    const int hf = ns >> 1, pr = (ns & 1) * 2;
                    MMA16816(acc[mt][ns], ar[mt][0], ar[mt][1], ar[mt][2], ar[mt][3],
                             br[hf][pr], br[hf][pr + 1]);
                }
        }
    }
    __syncthreads();    // all ldmatrix reads done before Qs/Vs overlay

    // epilogue: +bias; n<128 -> Qs, n>=128 -> Vs * head_en
    {
        const float he = head_en[h];
        const int r0 = (lane >> 2);
        const int cc = 2 * (lane & 3);
#pragma unroll
        for (int mt = 0; mt < 3; mt++) {
            int ta = mb + mt * 16 + r0;
            int tb2 = ta + 8;
#pragma unroll
            for (int ns = 0; ns < 4; ns++) {
                int n = nb + ns * 8 + cc;
                bool isv = (n >= 128);
                float* dst = isv ? Vs : Qs;
                int col = isv ? n - 128 : n;
                float scl = isv ? he : 1.f;
                float b0 = BiasS[n], b1 = BiasS[n + 1];
                if (ta < TT_) {
                    float2 o = make_float2((acc[mt][ns][0] + b0) * scl,
                                           (acc[mt][ns][1] + b1) * scl);
                    *(float2*)&dst[ta * QV_LD + col] = o;
                }
                if (tb2 < TT_) {
                    float2 o = make_float2((acc[mt][ns][2] + b0) * scl,
                                           (acc[mt][ns][3] + b1) * scl);
                    *(float2*)&dst[tb2 * QV_LD + col] = o;
                }
            }
        }
    }
    __syncthreads();

    // ---------------- P2: scores ----------------
    const float scale = 0.08838834764831843f;
    if (tid < 441) {
        const int t0s = (tid / 21) * 4;
        const int s0 = (tid % 21) * 4;
        int ti[4];
#pragma unroll
        for (int i = 0; i < 4; i++) ti[i] = min(t0s + i, TT_ - 1);
        unsigned long long sacc[4][4];
#pragma unroll
        for (int i = 0; i < 4; i++)
#pragma unroll
            for (int q = 0; q < 4; q++) sacc[i][q] = 0ULL;
#pragma unroll 1
        for (int d = 0; d < DD; d += 4) {
            const int dp = d >> 1;
            ulonglong2 q[4];
#pragma unroll
            for (int i = 0; i < 4; i++)
                q[i] = *(const ulonglong2*)&Qs[ti[i] * QV_LD + d];
            ulonglong2 ka = *(const ulonglong2*)&KT[(dp    ) * 168 + s0 * 2];
            ulonglong2 kb = *(const ulonglong2*)&KT[(dp    ) * 168 + s0 * 2 + 4];
            ulonglong2 kc = *(const ulonglong2*)&KT[(dp + 1) * 168 + s0 * 2];
            ulonglong2 kd = *(const ulonglong2*)&KT[(dp + 1) * 168 + s0 * 2 + 4];
#pragma unroll
            for (int i = 0; i < 4; i++) {
                unsigned long long u;
                u = add2(q[i].x, ka.x) & ABS2MASK;  sacc[i][0] = add2(sacc[i][0], u);
                u = add2(q[i].y, kc.x) & ABS2MASK;  sacc[i][0] = add2(sacc[i][0], u);
                u = add2(q[i].x, ka.y) & ABS2MASK;  sacc[i][1] = add2(sacc[i][1], u);
                u = add2(q[i].y, kc.y) & ABS2MASK;  sacc[i][1] = add2(sacc[i][1], u);
                u = add2(q[i].x, kb.x) & ABS2MASK;  sacc[i][2] = add2(sacc[i][2], u);
                u = add2(q[i].y, kd.x) & ABS2MASK;  sacc[i][2] = add2(sacc[i][2], u);
                u = add2(q[i].x, kb.y) & ABS2MASK;  sacc[i][3] = add2(sacc[i][3], u);
                u = add2(q[i].y, kd.y) & ABS2MASK;  sacc[i][3] = add2(sacc[i][3], u);
            }
        }
#pragma unroll
        for (int i = 0; i < 4; i++) {
            if (t0s + i >= TT_) continue;
#pragma unroll
            for (int q = 0; q < 4; q++) {
                if (s0 + q >= TT_) continue;
                float2 f = unpack2(sacc[i][q]);
                S[(s0 + q) * LDS_S + (t0s + i)] = -(f.x + f.y) * scale;
            }
        }
    }
    __syncthreads();

    // ---------------- P3: softmax over s ----------------
    if (tid < 352) {
        const int t  = tid >> 2;
        const int l4 = tid & 3;
        const bool valid = (t < TT_);
        const int sBeg = l4 * 21;
        const int sEnd = valid ? min(sBeg + 21, TT_) : sBeg;
        float mx = -1e30f;
        for (int s = sBeg; s < sEnd; s++) mx = fmaxf(mx, S[s * LDS_S + t]);
        mx = fmaxf(mx, __shfl_xor_sync(0xFFFFFFFFu, mx, 1));
        mx = fmaxf(mx, __shfl_xor_sync(0xFFFFFFFFu, mx, 2));
        float sum = 0.f;
        for (int s = sBeg; s < sEnd; s++) {
            float e = __expf(S[s * LDS_S + t] - mx);
            sum += e;
            S[s * LDS_S + t] = e;
        }
        sum += __shfl_xor_sync(0xFFFFFFFFu, sum, 1);
        sum += __shfl_xor_sync(0xFFFFFFFFu, sum, 2);
        float inv = 1.f / sum;
        for (int s = sBeg; s < sEnd; s++) {
            float mval = Msk[t * TT_ + s];
            float a = S[s * LDS_S + t] * inv * mval;
            S[s * LDS_S + t] = a;
            if (b == 0)
                ap_out[((size_t)t * TT_ + s) * HH + h] = a - 1.f + mval;
        }
    }
    __syncthreads();

    // ---------------- P4: AV -> g_bo ----------------
    float* bo = g_bo + (((size_t)b * HH + h) * TT_) * DD;
    if (tid < 336) {
        int t0a = (tid >> 4) * 4;
        int d0 = (tid & 15) * 8;
        unsigned long long av[4][4];
#pragma unroll
        for (int i = 0; i < 4; i++)
#pragma unroll
            for (int q = 0; q < 4; q++) av[i][q] = 0ULL;
#pragma unroll 2
        for (int s = 0; s < TT_; s++) {
            float4 a4 = *(const float4*)&S[s * LDS_S + t0a];
            ulonglong2 v0 = *(const ulonglong2*)&Vs[s * QV_LD + d0];
            ulonglong2 v1 = *(const ulonglong2*)&Vs[s * QV_LD + d0 + 4];
            unsigned long long p0 = pack2(a4.x), p1 = pack2(a4.y);
            unsigned long long p2 = pack2(a4.z), p3 = pack2(a4.w);
            av[0][0] = fma2(p0, v0.x, av[0][0]);  av[0][1] = fma2(p0, v0.y, av[0][1]);
            av[0][2] = fma2(p0, v1.x, av[0][2]);  av[0][3] = fma2(p0, v1.y, av[0][3]);
            av[1][0] = fma2(p1, v0.x, av[1][0]);  av[1][1] = fma2(p1, v0.y, av[1][1]);
            av[1][2] = fma2(p1, v1.x, av[1][2]);  av[1][3] = fma2(p1, v1.y, av[1][3]);
            av[2][0] = fma2(p2, v0.x, av[2][0]);  av[2][1] = fma2(p2, v0.y, av[2][1]);
            av[2][2] = fma2(p2, v1.x, av[2][2]);  av[2][3] = fma2(p2, v1.y, av[2][3]);
            av[3][0] = fma2(p3, v0.x, av[3][0]);  av[3][1] = fma2(p3, v0.y, av[3][1]);
            av[3][2] = fma2(p3, v1.x, av[3][2]);  av[3][3] = fma2(p3, v1.y, av[3][3]);
        }
#pragma unroll
        for (int i = 0; i < 4; i++) {
            int t = t0a + i;
            if (t >= TT_) continue;
            float2 q0 = unpack2(av[i][0]), q1 = unpack2(av[i][1]);
            float2 q2 = unpack2(av[i][2]), q3 = unpack2(av[i][3]);
            *(float4*)&bo[(size_t)t * DD + d0]     = make_float4(q0.x, q0.y, q1.x, q1.y);
            *(float4*)&bo[(size_t)t * DD + d0 + 4] = make_float4(q2.x, q2.y, q3.x, q3.y);
        }
    }
}

// ---------------------------------------------------------------------------
__device__ __forceinline__ float qgelu4(float s) {
    float u = s + 4.f;
    return u / (1.f + __expf(-1.702f * u)) - 4.f;
}

__global__ void __launch_bounds__(128) reduce_gelu_kernel() {
    int idx = blockIdx.x * 128 + threadIdx.x;
    int m  = idx >> 5, kq = idx & 31;
    int bb = m / TT_, t = m - bb * TT_;
    const float4* base = (const float4*)g_bo + ((size_t)(bb * HH) * TT_ + t) * 32 + kq;
    float s0 = 0.f, s1 = 0.f, s2 = 0.f, s3 = 0.f;
#pragma unroll
    for (int hh = 0; hh < HH; hh++) {
        float4 v = base[(size_t)hh * TT_ * 32];
        s0 += v.x; s1 += v.y; s2 += v.z; s3 += v.w;
    }
    float4 g;
    g.x = qgelu4(s0); g.y = qgelu4(s1); g.z = qgelu4(s2); g.w = qgelu4(s3);
    ((float4*)g_G)[(size_t)m * 32 + kq] = g;
}

__global__ void __launch_bounds__(256) fanout_kernel(const float* __restrict__ x,
                                                     const float* __restrict__ Wf,
                                                     const float* __restrict__ bf,
                                                     float* __restrict__ out) {
    extern __shared__ float sm[];
    float* Ws = sm;                 // [128][64]
    float* Gs = sm + 128 * 64;      // [128][17]
    const int LDG_ = 17;
    const int mtile = blockIdx.x >> 1;
    const int half  = blockIdx.x & 1;
    const int m0 = mtile * 16;
    const int nbase = half * 64;
    const int tid = threadIdx.x;
    {
        int n  = tid & 63, k4 = tid >> 6;
        const float* wr = Wf + (size_t)(nbase + n) * DD;
#pragma unroll
        for (int p = 0; p < 8; p++) {
            int kq = p * 4 + k4;
            float4 w = *(const float4*)(wr + kq * 4);
            Ws[(kq*4+0)*64 + n] = w.x;  Ws[(kq*4+1)*64 + n] = w.y;
            Ws[(kq*4+2)*64 + n] = w.z;  Ws[(kq*4+3)*64 + n] = w.w;
        }
    }
    {
#pragma unroll
        for (int p = 0; p < 2; p++) {
            int i  = p * 256 + tid;
            int ml = i >> 5, kq = i & 31;
            float4 g = ((const float4*)g_G)[(size_t)(m0 + ml) * 32 + kq];
            Gs[(kq*4+0)*LDG_ + ml] = g.x;  Gs[(kq*4+1)*LDG_ + ml] = g.y;
            Gs[(kq*4+2)*LDG_ + ml] = g.z;  Gs[(kq*4+3)*LDG_ + ml] = g.w;
        }
    }
    __syncthreads();
    const int m_ = tid >> 4;
    const int n0 = (tid & 15) * 4;
    float a0 = 0.f, a1 = 0.f, a2 = 0.f, a3 = 0.f;
#pragma unroll 8
    for (int k = 0; k < 128; k++) {
        float g = Gs[k * LDG_ + m_];
        float4 w = *(const float4*)&Ws[k * 64 + n0];
        a0 += g * w.x; a1 += g * w.y; a2 += g * w.z; a3 += g * w.w;
    }
    int m = m0 + m_, ng = nbase + n0;
    float4 xv = *(const float4*)&x[(size_t)m * DD + ng];
    float4 bv = *(const float4*)&bf[ng];
    *(float4*)&out[(size_t)m * DD + ng] =
        make_float4(xv.x + a0 + bv.x, xv.y + a1 + bv.y, xv.z + a2 + bv.z, xv.w + a3 + bv.w);
}

// ---------------------------------------------------------------------------
extern "C" void kernel_launch(void* const* d_in, const int* in_sizes, int n_in,
                              void* d_out, int out_size) {
    const float* x        = (const float*)d_in[0];
    const float* msk      = (const float*)d_in[1];
    const float* wqkv_w   = (const float*)d_in[2];
    const float* wqkv_b   = (const float*)d_in[3];
    const float* wk_w     = (const float*)d_in[4];
    const float* fanout_w = (const float*)d_in[5];
    const float* fanout_b = (const float*)d_in[6];
    const float* head_en  = (const float*)d_in[7];

    float* out = (float*)d_out;
    float* ap_out = out + (size_t)BT * DD;

    const int smemA = SMEM_FLOATS * 4;                   // 219360
    const int smemF = (128*64 + 128*17) * 4 + 16;

    cudaFuncSetAttribute(attn_mma,      cudaFuncAttributeMaxDynamicSharedMemorySize, smemA);
    cudaFuncSetAttribute(fanout_kernel, cudaFuncAttributeMaxDynamicSharedMemorySize, smemF);

    attn_mma<<<BB * HH, 512, smemA>>>(x, wqkv_w, wqkv_b, wk_w, msk, head_en, ap_out);

    reduce_gelu_kernel<<<324, 128>>>();

    fanout_kernel<<<162, 256, smemF>>>(x, fanout_w, fanout_b, out);
}

// round 14
// speedup vs baseline: 1.5377x; 1.1021x over previous
#include <cuda_runtime.h>
#include <cuda_bf16.h>
#include <math.h>
#include <stdint.h>

#define BB 16
#define TT_ 81
#define DD 128
#define HH 8
#define BT (BB*TT_)       // 1296

__device__ float g_bo[BB*HH*TT_*DD];
__device__ float g_G[BT*DD];

// ---------------- packed fp32x2 helpers ----------------
static __device__ __forceinline__ unsigned long long add2(unsigned long long a,
                                                          unsigned long long b) {
    unsigned long long r;
    asm("add.rn.f32x2 %0, %1, %2;" : "=l"(r) : "l"(a), "l"(b));
    return r;
}
static __device__ __forceinline__ float2 unpack2(unsigned long long v) {
    float2 f;
    asm("mov.b64 {%0, %1}, %2;" : "=f"(f.x), "=f"(f.y) : "l"(v));
    return f;
}
#define ABS2MASK 0x7FFFFFFF7FFFFFFFULL

static __device__ __forceinline__ uint32_t smem_to_u32(const void* p) {
    uint32_t a;
    asm("{ .reg .u64 t; cvta.to.shared.u64 t, %1; cvt.u32.u64 %0, t; }" : "=r"(a) : "l"(p));
    return a;
}
#define LDMX4(r0, r1, r2, r3, addr) \
    asm volatile("ldmatrix.sync.aligned.m8n8.x4.shared.b16 {%0,%1,%2,%3}, [%4];" \
        : "=r"(r0), "=r"(r1), "=r"(r2), "=r"(r3) : "r"(addr))
#define MMA16816(c, a0, a1, a2, a3, b0, b1) \
    asm volatile("mma.sync.aligned.m16n8k16.row.col.f32.bf16.bf16.f32 " \
        "{%0,%1,%2,%3}, {%4,%5,%6,%7}, {%8,%9}, {%0,%1,%2,%3};" \
        : "+f"((c)[0]), "+f"((c)[1]), "+f"((c)[2]), "+f"((c)[3]) \
        : "r"(a0), "r"(a1), "r"(a2), "r"(a3), "r"(b0), "r"(b1))

// split 8 floats -> bf16-hi uint4 + bf16-lo uint4
static __device__ __forceinline__ void split8(float4 a, float4 b, uint4& hi, uint4& lo) {
    float va[8] = {a.x, a.y, a.z, a.w, b.x, b.y, b.z, b.w};
    unsigned short h[8], l[8];
#pragma unroll
    for (int i = 0; i < 8; i++) {
        __nv_bfloat16 bh = __float2bfloat16(va[i]);
        h[i] = __bfloat16_as_ushort(bh);
        l[i] = __bfloat16_as_ushort(__float2bfloat16(va[i] - __bfloat162float(bh)));
    }
    hi = make_uint4((uint32_t)h[0]|((uint32_t)h[1]<<16), (uint32_t)h[2]|((uint32_t)h[3]<<16),
                    (uint32_t)h[4]|((uint32_t)h[5]<<16), (uint32_t)h[6]|((uint32_t)h[7]<<16));
    lo = make_uint4((uint32_t)l[0]|((uint32_t)l[1]<<16), (uint32_t)l[2]|((uint32_t)l[3]<<16),
                    (uint32_t)l[4]|((uint32_t)l[5]<<16), (uint32_t)l[6]|((uint32_t)l[7]<<16));
}
// cvt-only: 8 floats -> bf16-hi uint4
static __device__ __forceinline__ uint4 cvt8(float4 a, float4 b) {
    float va[8] = {a.x, a.y, a.z, a.w, b.x, b.y, b.z, b.w};
    unsigned short h[8];
#pragma unroll
    for (int i = 0; i < 8; i++) h[i] = __bfloat16_as_ushort(__float2bfloat16(va[i]));
    return make_uint4((uint32_t)h[0]|((uint32_t)h[1]<<16), (uint32_t)h[2]|((uint32_t)h[3]<<16),
                      (uint32_t)h[4]|((uint32_t)h[5]<<16), (uint32_t)h[6]|((uint32_t)h[7]<<16));
}

// ---- smem layout ----
// GEMM phase (bytes): Ahi[96][136]bf16 @0, Alo @26112, W[256][136]bf16 @52224..121856
// post-GEMM overlays:
//   Qs f32 [81][132] @0 (live P2)              -> Sbhi[96][104]bf16 @0, Sblo @19968 (written P3)
//   VThi[128][104]bf16 @52224, VTlo @78848     (written in epilogue, over W)
//   KT @121856, S fp32 @164864, Msk @192080, Bias @218336
#define AHI_B   0
#define ALO_B   26112
#define WB_B    52224
#define SBHI_B  0
#define SBLO_B  19968
#define VTHI_B  52224
#define VTLO_B  78848
#define KT_F    30464
#define LDS_S   84
#define S_F     41216
#define MSK_F   48020
#define BIAS_F  54584
#define SMEM_FLOATS (BIAS_F + 256)   // 54840 fl = 219360 B
#define QV_LD   132
#define SB_LD   208                  // bytes per Sb / VT row (104 bf16)

__global__ void __launch_bounds__(512, 1)
attn_mma(const float* __restrict__ x,
         const float* __restrict__ wqkv_w,
         const float* __restrict__ wqkv_b,
         const float* __restrict__ wk_w,
         const float* __restrict__ msk,
         const float* __restrict__ head_en,
         float* __restrict__ ap_out) {
    extern __shared__ float sm[];
    char* smb = (char*)sm;
    const uint32_t sb = smem_to_u32(sm);
    float* Qs  = sm;                 // stride 132, overlays A after GEMM
    float* KT  = sm + KT_F;
    float* S   = sm + S_F;
    float* Msk = sm + MSK_F;
    float* BiasS = sm + BIAS_F;

    const int b = blockIdx.x >> 3;
    const int h = blockIdx.x & 7;
    const int tid = threadIdx.x;
    const int wid = tid >> 5;
    const int lane = tid & 31;

    const float* xb = x + (size_t)b * TT_ * DD;
    const float* Wg = wqkv_w + ((size_t)h * 2 * DD) * DD;   // 256 x 128

    // ---------------- S1: stage A hi/lo, W hi, bias, KT, Msk ----------------
    for (int idx = tid; idx < 96 * 16; idx += 512) {        // A: (t, k8)
        int t = idx >> 4, k0 = (idx & 15) << 3;
        uint4 hi = make_uint4(0, 0, 0, 0), lo = make_uint4(0, 0, 0, 0);
        if (t < TT_) {
            float4 va = *(const float4*)(xb + t * DD + k0);
            float4 vb = *(const float4*)(xb + t * DD + k0 + 4);
            split8(va, vb, hi, lo);
        }
        uint32_t off = (uint32_t)t * 272 + (uint32_t)k0 * 2;
        *(uint4*)(smb + AHI_B + off) = hi;
        *(uint4*)(smb + ALO_B + off) = lo;
    }
    for (int idx = tid; idx < 256 * 16; idx += 512) {       // W hi only: (n, k8)
        int n = idx >> 4, k0 = (idx & 15) << 3;
        float4 va = *(const float4*)(Wg + (size_t)n * DD + k0);
        float4 vb = *(const float4*)(Wg + (size_t)n * DD + k0 + 4);
        *(uint4*)(smb + WB_B + (uint32_t)n * 272 + (uint32_t)k0 * 2) = cvt8(va, vb);
    }
    if (tid < 256) BiasS[tid] = wqkv_b[h * 256 + tid];
    {   // KT (negated k), Msk
        const float4* x4  = (const float4*)xb;
        const float4* wk4 = (const float4*)(wk_w + h * DD);
        for (int i = tid; i < 32 * TT_; i += 512) {
            int dq = i / TT_, t = i - dq * TT_;
            float4 xv = x4[t * 32 + dq];
            float4 wv = wk4[dq];
            int dp = dq * 2;
            *(float2*)&KT[(dp    ) * 168 + t * 2] = make_float2(-(xv.x*wv.x), -(xv.y*wv.y));
            *(float2*)&KT[(dp + 1) * 168 + t * 2] = make_float2(-(xv.z*wv.z), -(xv.w*wv.w));
        }
        for (int i = tid; i < 192; i += 512) {
            int dp = i / 3, s = 81 + (i % 3);
            *(float2*)&KT[dp * 168 + s * 2] = make_float2(0.f, 0.f);
        }
        const float* mg = msk + (size_t)h * TT_ * TT_;
        for (int i = tid; i < TT_ * TT_; i += 512) Msk[i] = mg[i];
    }
    __syncthreads();

    // ---------------- QKV GEMM: 16 warps x (3 m16 x 4 n8), 2 passes ----------------
    const int mgrp = wid >> 3, ngrp = wid & 7;
    const int mb = mgrp * 48, nb = ngrp * 32;
    const int j = lane >> 3, lr = lane & 7;
    const uint32_t aOff = (uint32_t)(mb + ((j & 1) << 3) + lr) * 272 + ((uint32_t)(j >> 1) << 4);
    const uint32_t bOff = (uint32_t)(nb + ((j >> 1) << 3) + lr) * 272 + ((uint32_t)(j & 1) << 4);
    const uint32_t aHi = sb + AHI_B + aOff;
    const uint32_t aLo = sb + ALO_B + aOff;
    const uint32_t bBs = sb + WB_B + bOff;

    {
        float acc[3][4][4];
#pragma unroll
        for (int m = 0; m < 3; m++)
#pragma unroll
            for (int n = 0; n < 4; n++)
#pragma unroll
                for (int q = 0; q < 4; q++) acc[m][n][q] = 0.f;

#pragma unroll
        for (int pass = 0; pass < 2; pass++) {
            const uint32_t aB = (pass == 1) ? aLo : aHi;
#pragma unroll
            for (int ks = 0; ks < 8; ks++) {
                const uint32_t ko = (uint32_t)ks * 32;
                uint32_t ar[3][4], br[2][4];
#pragma unroll
                for (int mt = 0; mt < 3; mt++)
                    LDMX4(ar[mt][0], ar[mt][1], ar[mt][2], ar[mt][3],
                          aB + (uint32_t)mt * (16 * 272) + ko);
#pragma unroll
                for (int hf = 0; hf < 2; hf++)
                    LDMX4(br[hf][0], br[hf][1], br[hf][2], br[hf][3],
                          bBs + (uint32_t)hf * (16 * 272) + ko);
#pragma unroll
                for (int mt = 0; mt < 3; mt++)
#pragma unroll
                    for (int ns = 0; ns < 4; ns++) {
                        const int hf = ns >> 1, pr = (ns & 1) * 2;
                        MMA16816(acc[mt][ns], ar[mt][0], ar[mt][1], ar[mt][2], ar[mt][3],
                                 br[hf][pr], br[hf][pr + 1]);
                    }
            }
        }
        __syncthreads();    // all ldmatrix reads done before overlays

        // epilogue: +bias; n<128 -> Qs fp32; n>=128 -> VThi/VTlo bf16 [d][s]
        const float he = head_en[h];
        const int r0 = (lane >> 2);
        const int cc = 2 * (lane & 3);
#pragma unroll
        for (int mt = 0; mt < 3; mt++) {
            int rows[2] = { mb + mt * 16 + r0, mb + mt * 16 + r0 + 8 };
#pragma unroll
            for (int ns = 0; ns < 4; ns++) {
                int n = nb + ns * 8 + cc;
                float b0 = BiasS[n], b1 = BiasS[n + 1];
#pragma unroll
                for (int half = 0; half < 2; half++) {
                    int t = rows[half];
                    if (t >= TT_) continue;
                    float v0 = acc[mt][ns][half * 2]     + b0;
                    float v1 = acc[mt][ns][half * 2 + 1] + b1;
                    if (n < 128) {
                        *(float2*)&Qs[t * QV_LD + n] = make_float2(v0, v1);
                    } else {
                        int col = n - 128;
                        float w0 = v0 * he, w1 = v1 * he;
                        __nv_bfloat16 h0 = __float2bfloat16(w0);
                        __nv_bfloat16 h1 = __float2bfloat16(w1);
                        *(__nv_bfloat16*)(smb + VTHI_B + (uint32_t)col * SB_LD + t * 2) = h0;
                        *(__nv_bfloat16*)(smb + VTHI_B + (uint32_t)(col + 1) * SB_LD + t * 2) = h1;
                        *(__nv_bfloat16*)(smb + VTLO_B + (uint32_t)col * SB_LD + t * 2) =
                            __float2bfloat16(w0 - __bfloat162float(h0));
                        *(__nv_bfloat16*)(smb + VTLO_B + (uint32_t)(col + 1) * SB_LD + t * 2) =
                            __float2bfloat16(w1 - __bfloat162float(h1));
                    }
                }
            }
        }
        // zero VT pad cols s=81..95 for all 128 d, both mats
        for (int i = tid; i < 1920; i += 512) {
            int d = i / 15, s = 81 + (i % 15);
            *(__nv_bfloat16*)(smb + VTHI_B + (uint32_t)d * SB_LD + s * 2) = __float2bfloat16(0.f);
            *(__nv_bfloat16*)(smb + VTLO_B + (uint32_t)d * SB_LD + s * 2) = __float2bfloat16(0.f);
        }
    }
    __syncthreads();

    // ---------------- P2: scores (fp32, f32x2+AND) ----------------
    const float scale = 0.08838834764831843f;
    if (tid < 441) {
        const int t0s = (tid / 21) * 4;
        const int s0 = (tid % 21) * 4;
        int ti[4];
#pragma unroll
        for (int i = 0; i < 4; i++) ti[i] = min(t0s + i, TT_ - 1);
        unsigned long long sacc[4][4];
#pragma unroll
        for (int i = 0; i < 4; i++)
#pragma unroll
            for (int q = 0; q < 4; q++) sacc[i][q] = 0ULL;
#pragma unroll 1
        for (int d = 0; d < DD; d += 4) {
            const int dp = d >> 1;
            ulonglong2 q[4];
#pragma unroll
            for (int i = 0; i < 4; i++)
                q[i] = *(const ulonglong2*)&Qs[ti[i] * QV_LD + d];
            ulonglong2 ka = *(const ulonglong2*)&KT[(dp    ) * 168 + s0 * 2];
            ulonglong2 kb = *(const ulonglong2*)&KT[(dp    ) * 168 + s0 * 2 + 4];
            ulonglong2 kc = *(const ulonglong2*)&KT[(dp + 1) * 168 + s0 * 2];
            ulonglong2 kd = *(const ulonglong2*)&KT[(dp + 1) * 168 + s0 * 2 + 4];
#pragma unroll
            for (int i = 0; i < 4; i++) {
                unsigned long long u;
                u = add2(q[i].x, ka.x) & ABS2MASK;  sacc[i][0] = add2(sacc[i][0], u);
                u = add2(q[i].y, kc.x) & ABS2MASK;  sacc[i][0] = add2(sacc[i][0], u);
                u = add2(q[i].x, ka.y) & ABS2MASK;  sacc[i][1] = add2(sacc[i][1], u);
                u = add2(q[i].y, kc.y) & ABS2MASK;  sacc[i][1] = add2(sacc[i][1], u);
                u = add2(q[i].x, kb.x) & ABS2MASK;  sacc[i][2] = add2(sacc[i][2], u);
                u = add2(q[i].y, kd.x) & ABS2MASK;  sacc[i][2] = add2(sacc[i][2], u);
                u = add2(q[i].x, kb.y) & ABS2MASK;  sacc[i][3] = add2(sacc[i][3], u);
                u = add2(q[i].y, kd.y) & ABS2MASK;  sacc[i][3] = add2(sacc[i][3], u);
            }
        }
#pragma unroll
        for (int i = 0; i < 4; i++) {
            if (t0s + i >= TT_) continue;
#pragma unroll
            for (int q = 0; q < 4; q++) {
                if (s0 + q >= TT_) continue;
                float2 f = unpack2(sacc[i][q]);
                S[(s0 + q) * LDS_S + (t0s + i)] = -(f.x + f.y) * scale;
            }
        }
    }
    __syncthreads();

    // ---------------- P3: softmax; writes Sbhi/Sblo [t][s] bf16 + ap ----------------
    if (tid < 352) {
        const int t  = tid >> 2;
        const int l4 = tid & 3;
        const bool valid = (t < TT_);
        const int sBeg = l4 * 21;
        const int sEnd = valid ? min(sBeg + 21, TT_) : sBeg;
        float mx = -1e30f;
        for (int s = sBeg; s < sEnd; s++) mx = fmaxf(mx, S[s * LDS_S + t]);
        mx = fmaxf(mx, __shfl_xor_sync(0xFFFFFFFFu, mx, 1));
        mx = fmaxf(mx, __shfl_xor_sync(0xFFFFFFFFu, mx, 2));
        float sum = 0.f;
        for (int s = sBeg; s < sEnd; s++) {
            float e = __expf(S[s * LDS_S + t] - mx);
            sum += e;
            S[s * LDS_S + t] = e;
        }
        sum += __shfl_xor_sync(0xFFFFFFFFu, sum, 1);
        sum += __shfl_xor_sync(0xFFFFFFFFu, sum, 2);
        float inv = 1.f / sum;
        for (int s = sBeg; s < sEnd; s++) {
            float mval = Msk[t * TT_ + s];
            float a = S[s * LDS_S + t] * inv * mval;
            __nv_bfloat16 hv = __float2bfloat16(a);
            *(__nv_bfloat16*)(smb + SBHI_B + (uint32_t)t * SB_LD + s * 2) = hv;
            *(__nv_bfloat16*)(smb + SBLO_B + (uint32_t)t * SB_LD + s * 2) =
                __float2bfloat16(a - __bfloat162float(hv));
            if (b == 0)
                ap_out[((size_t)t * TT_ + s) * HH + h] = a - 1.f + mval;
        }
    } else {
        // zero Sb pads: t rows 81..95 full; s cols 81..95 for t<=80 (both mats)
        for (int i = tid - 352; i < 780; i += 160) {
            int row = 81 + i / 52, w = i % 52;
            *(uint32_t*)(smb + SBHI_B + (uint32_t)row * SB_LD + w * 4) = 0u;
            *(uint32_t*)(smb + SBLO_B + (uint32_t)row * SB_LD + w * 4) = 0u;
        }
        for (int i = tid - 352; i < 1215; i += 160) {
            int t = i / 15, s = 81 + (i % 15);
            *(__nv_bfloat16*)(smb + SBHI_B + (uint32_t)t * SB_LD + s * 2) = __float2bfloat16(0.f);
            *(__nv_bfloat16*)(smb + SBLO_B + (uint32_t)t * SB_LD + s * 2) = __float2bfloat16(0.f);
        }
    }
    __syncthreads();

    // ---------------- P4: AV via HMMA, 3 passes -> g_bo ----------------
    {
        const int mb2 = (wid >> 3) * 48;        // 2 m-groups x 3 m16
        const int nb2 = (wid & 7) * 16;         // 8 n-groups x 2 n8
        const uint32_t aOffAV = (uint32_t)(mb2 + ((j & 1) << 3) + lr) * SB_LD + ((uint32_t)(j >> 1) << 4);
        const uint32_t bOffAV = (uint32_t)(nb2 + ((j >> 1) << 3) + lr) * SB_LD + ((uint32_t)(j & 1) << 4);

        float av[3][2][4];
#pragma unroll
        for (int m = 0; m < 3; m++)
#pragma unroll
            for (int n = 0; n < 2; n++)
#pragma unroll
                for (int q = 0; q < 4; q++) av[m][n][q] = 0.f;

#pragma unroll
        for (int pass = 0; pass < 3; pass++) {
            const uint32_t aB = sb + ((pass == 1) ? SBLO_B : SBHI_B) + aOffAV;
            const uint32_t bB = sb + ((pass == 2) ? VTLO_B : VTHI_B) + bOffAV;
#pragma unroll
            for (int ks = 0; ks < 6; ks++) {
                const uint32_t ko = (uint32_t)ks * 32;
                uint32_t ar[3][4], br[4];
#pragma unroll
                for (int mt = 0; mt < 3; mt++)
                    LDMX4(ar[mt][0], ar[mt][1], ar[mt][2], ar[mt][3],
                          aB + (uint32_t)mt * (16 * SB_LD) + ko);
                LDMX4(br[0], br[1], br[2], br[3], bB + ko);
#pragma unroll
                for (int mt = 0; mt < 3; mt++)
#pragma unroll
                    for (int ns = 0; ns < 2; ns++)
                        MMA16816(av[mt][ns], ar[mt][0], ar[mt][1], ar[mt][2], ar[mt][3],
                                 br[ns * 2], br[ns * 2 + 1]);
            }
        }

        float* bo = g_bo + (((size_t)b * HH + h) * TT_) * DD;
        const int r0 = (lane >> 2);
        const int cc = 2 * (lane & 3);
#pragma unroll
        for (int mt = 0; mt < 3; mt++) {
            int rows[2] = { mb2 + mt * 16 + r0, mb2 + mt * 16 + r0 + 8 };
#pragma unroll
            for (int ns = 0; ns < 2; ns++) {
                int d = nb2 + ns * 8 + cc;
#pragma unroll
                for (int half = 0; half < 2; half++) {
                    int t = rows[half];
                    if (t >= TT_) continue;
                    *(float2*)&bo[(size_t)t * DD + d] =
                        make_float2(av[mt][ns][half * 2], av[mt][ns][half * 2 + 1]);
                }
            }
        }
    }
}

// ---------------------------------------------------------------------------
__device__ __forceinline__ float qgelu4(float s) {
    float u = s + 4.f;
    return u / (1.f + __expf(-1.702f * u)) - 4.f;
}

__global__ void __launch_bounds__(128) reduce_gelu_kernel() {
    int idx = blockIdx.x * 128 + threadIdx.x;
    int m  = idx >> 5, kq = idx & 31;
    int bb = m / TT_, t = m - bb * TT_;
    const float4* base = (const float4*)g_bo + ((size_t)(bb * HH) * TT_ + t) * 32 + kq;
    float s0 = 0.f, s1 = 0.f, s2 = 0.f, s3 = 0.f;
#pragma unroll
    for (int hh = 0; hh < HH; hh++) {
        float4 v = base[(size_t)hh * TT_ * 32];
        s0 += v.x; s1 += v.y; s2 += v.z; s3 += v.w;
    }
    float4 g;
    g.x = qgelu4(s0); g.y = qgelu4(s1); g.z = qgelu4(s2); g.w = qgelu4(s3);
    ((float4*)g_G)[(size_t)m * 32 + kq] = g;
}

__global__ void __launch_bounds__(256) fanout_kernel(const float* __restrict__ x,
                                                     const float* __restrict__ Wf,
                                                     const float* __restrict__ bf,
                                                     float* __restrict__ out) {
    extern __shared__ float sm[];
    float* Ws = sm;                 // [128][64]
    float* Gs = sm + 128 * 64;      // [128][17]
    const int LDG_ = 17;
    const int mtile = blockIdx.x >> 1;
    const int half  = blockIdx.x & 1;
    const int m0 = mtile * 16;
    const int nbase = half * 64;
    const int tid = threadIdx.x;
    {
        int n  = tid & 63, k4 = tid >> 6;
        const float* wr = Wf + (size_t)(nbase + n) * DD;
#pragma unroll
        for (int p = 0; p < 8; p++) {
            int kq = p * 4 + k4;
            float4 w = *(const float4*)(wr + kq * 4);
            Ws[(kq*4+0)*64 + n] = w.x;  Ws[(kq*4+1)*64 + n] = w.y;
            Ws[(kq*4+2)*64 + n] = w.z;  Ws[(kq*4+3)*64 + n] = w.w;
        }
    }
    {
#pragma unroll
        for (int p = 0; p < 2; p++) {
            int i  = p * 256 + tid;
            int ml = i >> 5, kq = i & 31;
            float4 g = ((const float4*)g_G)[(size_t)(m0 + ml) * 32 + kq];
            Gs[(kq*4+0)*LDG_ + ml] = g.x;  Gs[(kq*4+1)*LDG_ + ml] = g.y;
            Gs[(kq*4+2)*LDG_ + ml] = g.z;  Gs[(kq*4+3)*LDG_ + ml] = g.w;
        }
    }
    __syncthreads();
    const int m_ = tid >> 4;
    const int n0 = (tid & 15) * 4;
    float a0 = 0.f, a1 = 0.f, a2 = 0.f, a3 = 0.f;
#pragma unroll 8
    for (int k = 0; k < 128; k++) {
        float g = Gs[k * LDG_ + m_];
        float4 w = *(const float4*)&Ws[k * 64 + n0];
        a0 += g * w.x; a1 += g * w.y; a2 += g * w.z; a3 += g * w.w;
    }
    int m = m0 + m_, ng = nbase + n0;
    float4 xv = *(const float4*)&x[(size_t)m * DD + ng];
    float4 bv = *(const float4*)&bf[ng];
    *(float4*)&out[(size_t)m * DD + ng] =
        make_float4(xv.x + a0 + bv.x, xv.y + a1 + bv.y, xv.z + a2 + bv.z, xv.w + a3 + bv.w);
}

// ---------------------------------------------------------------------------
extern "C" void kernel_launch(void* const* d_in, const int* in_sizes, int n_in,
                              void* d_out, int out_size) {
    const float* x        = (const float*)d_in[0];
    const float* msk      = (const float*)d_in[1];
    const float* wqkv_w   = (const float*)d_in[2];
    const float* wqkv_b   = (const float*)d_in[3];
    const float* wk_w     = (const float*)d_in[4];
    const float* fanout_w = (const float*)d_in[5];
    const float* fanout_b = (const float*)d_in[6];
    const float* head_en  = (const float*)d_in[7];

    float* out = (float*)d_out;
    float* ap_out = out + (size_t)BT * DD;

    const int smemA = SMEM_FLOATS * 4;                   // 219360
    const int smemF = (128*64 + 128*17) * 4 + 16;

    cudaFuncSetAttribute(attn_mma,      cudaFuncAttributeMaxDynamicSharedMemorySize, smemA);
    cudaFuncSetAttribute(fanout_kernel, cudaFuncAttributeMaxDynamicSharedMemorySize, smemF);

    attn_mma<<<BB * HH, 512, smemA>>>(x, wqkv_w, wqkv_b, wk_w, msk, head_en, ap_out);

    reduce_gelu_kernel<<<324, 128>>>();

    fanout_kernel<<<162, 256, smemF>>>(x, fanout_w, fanout_b, out);
}